// round 13
// baseline (speedup 1.0000x reference)
#include <cuda_runtime.h>
#include <cuda_fp16.h>
#include <math.h>

#define TT 512
#define BB 128
#define HH 512
#define NZ 2048
#define TB 65536

// ---------------- static device scratch ----------------
__device__ float g_zx[(size_t)TB*NZ];
__device__ float g_hpre[(size_t)TB*HH];
__device__ __half g_Ah[(size_t)TB*HH];           // fp16 GEMM A staging (reused)
__device__ __half g_wBh[2048*512];               // fp16 GEMM B, [n][k]
__device__ unsigned g_WhpU[2][(size_t)NZ*HH/2];  // half2: [(nc*4+p%4)*64 + p/4]
__device__ unsigned g_hbufU[2][BB*HH/2];         // half2: [(row*4+p%4)*64 + p/4]
__device__ unsigned char g_rst[TB];
__device__ unsigned g_cnt[8], g_gen[8];
__device__ int g_rmode;

__device__ __forceinline__ void mma16(float* c, const unsigned* a, const unsigned* b){
  asm volatile("mma.sync.aligned.m16n8k16.row.col.f32.f16.f16.f32 "
    "{%0,%1,%2,%3},{%4,%5,%6,%7},{%8,%9},{%0,%1,%2,%3};"
    : "+f"(c[0]),"+f"(c[1]),"+f"(c[2]),"+f"(c[3])
    : "r"(a[0]),"r"(a[1]),"r"(a[2]),"r"(a[3]),"r"(b[0]),"r"(b[1]));
}
__device__ __forceinline__ void cpa16(void* dst, const void* src){
  unsigned d = (unsigned)__cvta_generic_to_shared(dst);
  asm volatile("cp.async.cg.shared.global [%0], [%1], 16;" :: "r"(d), "l"(src));
}
__device__ __forceinline__ float tanhx(float x){
  return 1.f - __fdividef(2.f, __expf(2.f*x) + 1.f);
}

// ---------------- resets dtype detect + convert ----------------
__global__ void detect_resets(const unsigned char* p){
  __shared__ int cF, c1;
  if (threadIdx.x == 0){ cF = 0; c1 = 0; }
  __syncthreads();
  for (int i = threadIdx.x; i < 65536; i += 256){
    unsigned char v = p[i];
    if (v == 0x3f || v == 0x80) atomicAdd(&cF, 1);
    else if (v == 1 && (i & 3)) atomicAdd(&c1, 1);
  }
  __syncthreads();
  if (threadIdx.x == 0) g_rmode = cF ? 2 : (c1 ? 1 : 0);
}
__global__ void conv_resets(const void* p){
  int i = blockIdx.x*blockDim.x + threadIdx.x;
  int m = g_rmode;
  bool z;
  if (m == 1)      z = ((const unsigned char*)p)[i] != 0;
  else if (m == 2) z = ((const float*)p)[i] != 0.f;
  else             z = ((const int*)p)[i] != 0;
  g_rst[i] = z ? 1 : 0;
}

// ---------------- fp32 -> fp16 A staging ----------------
__global__ void conv_x(const float* __restrict__ X, size_t n4){
  size_t i = (size_t)blockIdx.x*blockDim.x + threadIdx.x;
  if (i < n4){
    float4 v = *(const float4*)&X[i*4];
    unsigned lo = __half_as_ushort(__float2half(v.x)) |
                  ((unsigned)__half_as_ushort(__float2half(v.y)) << 16);
    unsigned hi = __half_as_ushort(__float2half(v.z)) |
                  ((unsigned)__half_as_ushort(__float2half(v.w)) << 16);
    ((uint2*)g_Ah)[i] = make_uint2(lo, hi);
  }
}

// ---------------- B transpose+convert: [k][N] f32 -> [n][512] f16 ----------
__global__ void pack_bh(const float* __restrict__ B, int N){
  __shared__ float t[32][33];
  int bx = blockIdx.x*32, by = blockIdx.y*32;
  int lx = threadIdx.x & 31, ly = threadIdx.x >> 5;
  #pragma unroll
  for (int q = 0; q < 32; q += 8)
    t[ly+q][lx] = B[(size_t)(by+ly+q)*N + bx+lx];
  __syncthreads();
  #pragma unroll
  for (int q = 0; q < 32; q += 8)
    g_wBh[(size_t)(bx+ly+q)*512 + by+lx] = __float2half(t[lx][ly+q]);
}

// pack Wh[512][2048] -> fp16 pair-packed layout
__global__ void pack_wh(const float* __restrict__ Wh, int L){
  __half* dst = (__half*)g_WhpU[L];
  for (size_t idx = blockIdx.x*blockDim.x + threadIdx.x; idx < (size_t)HH*NZ;
       idx += (size_t)gridDim.x*blockDim.x){
    int k = idx >> 11, j = idx & (NZ-1);
    int g = j >> 9, r = j & 511;
    int nc = ((r >> 4) << 6) + (g << 4) + (r & 15);
    int p = k >> 1;
    dst[(((size_t)nc*4 + (p & 3))*64 + (p >> 2))*2 + (k & 1)] = __float2half(Wh[idx]);
  }
}

// init h buffer (fp16) with reset for t=0 pre-applied + counters
__global__ void init_rec(const float* __restrict__ carryH){
  int i = blockIdx.x*blockDim.x + threadIdx.x;
  if (i < BB*HH){
    int row = i >> 9, col = i & 511;
    float v = g_rst[row] ? 0.f : carryH[i];
    int p = col >> 1;
    ((__half*)g_hbufU[0])[((row*4 + (p & 3))*64 + (p >> 2))*2 + (col & 1)] = __float2half(v);
  }
  if (i < 8){ g_cnt[i] = 0u; g_gen[i] = 0u; }
}

// ---------------- bulk fp16 GEMM (4-stage cp.async) ----------------
#define GS 20
#define NSTG 4
#define GEMM_SMEM (2*NSTG*128*GS*4)
#define HA(st,r,p) shA[((st)*128+(r))*GS + (p)]
#define HB(st,n,p) shB[((st)*128+(n))*GS + (p)]

template<bool RELU>
__global__ __launch_bounds__(256,2) void gemm_h(
    const float* __restrict__ bias, int cSel, int N)
{
  extern __shared__ unsigned shu[];
  unsigned* shA = shu;
  unsigned* shB = shu + NSTG*128*GS;
  float* C = (cSel == 1) ? g_hpre : g_zx;
  const int mt = blockIdx.y, nt = blockIdx.x, tid = threadIdx.x;
  const int wid = tid >> 5, lane = tid & 31, gID = lane >> 2, tig = lane & 3;
  const int wM = wid >> 1, wN = wid & 1;

  float acc[2][8][4];
  #pragma unroll
  for (int mi = 0; mi < 2; mi++)
    #pragma unroll
    for (int ni = 0; ni < 8; ni++)
      #pragma unroll
      for (int q = 0; q < 4; q++) acc[mi][ni][q] = 0.f;

  auto issue = [&](int kt, int st){
    #pragma unroll
    for (int i = 0; i < 2; i++){
      int c = tid + i*256, r = c >> 2, po = c & 3;
      cpa16(&HA(st, r, po*4), &g_Ah[(size_t)(mt*128 + r)*512 + kt*32 + po*8]);
    }
    #pragma unroll
    for (int i = 0; i < 2; i++){
      int c = tid + i*256, n = c >> 2, po = c & 3;
      cpa16(&HB(st, n, po*4), &g_wBh[(size_t)(nt*128 + n)*512 + kt*32 + po*8]);
    }
    asm volatile("cp.async.commit_group;" ::: "memory");
  };

  issue(0, 0); issue(1, 1); issue(2, 2); issue(3, 3);
  int st = 0;
  for (int kt = 0; kt < 16; kt++){
    if (kt <= 12)      asm volatile("cp.async.wait_group 3;" ::: "memory");
    else if (kt == 13) asm volatile("cp.async.wait_group 2;" ::: "memory");
    else if (kt == 14) asm volatile("cp.async.wait_group 1;" ::: "memory");
    else               asm volatile("cp.async.wait_group 0;" ::: "memory");
    __syncthreads();
    #pragma unroll
    for (int kk = 0; kk < 2; kk++){
      int off = kk*8;
      unsigned a[2][4], b[8][2];
      #pragma unroll
      for (int mi = 0; mi < 2; mi++){
        int r0 = wM*32 + mi*16 + gID;
        a[mi][0] = HA(st, r0,   tig + off);
        a[mi][1] = HA(st, r0+8, tig + off);
        a[mi][2] = HA(st, r0,   tig + 4 + off);
        a[mi][3] = HA(st, r0+8, tig + 4 + off);
      }
      #pragma unroll
      for (int ni = 0; ni < 8; ni++){
        int n0 = wN*64 + ni*8 + gID;
        b[ni][0] = HB(st, n0, tig + off);
        b[ni][1] = HB(st, n0, tig + 4 + off);
      }
      #pragma unroll
      for (int mi = 0; mi < 2; mi++)
        #pragma unroll
        for (int ni = 0; ni < 8; ni++)
          mma16(acc[mi][ni], a[mi], b[ni]);
    }
    __syncthreads();
    if (kt + NSTG < 16) issue(kt + NSTG, st);
    st = (st == NSTG-1) ? 0 : st + 1;
  }

  #pragma unroll
  for (int mi = 0; mi < 2; mi++){
    int r0 = mt*128 + wM*32 + mi*16 + gID;
    #pragma unroll
    for (int ni = 0; ni < 8; ni++){
      int col = nt*128 + wN*64 + ni*8 + tig*2;
      float b0 = bias[col], b1 = bias[col+1];
      float v0 = acc[mi][ni][0]+b0, v1 = acc[mi][ni][1]+b1;
      float v2 = acc[mi][ni][2]+b0, v3 = acc[mi][ni][3]+b1;
      if (RELU){ v0=fmaxf(v0,0.f); v1=fmaxf(v1,0.f); v2=fmaxf(v2,0.f); v3=fmaxf(v3,0.f); }
      *(float2*)&C[(size_t)r0*N + col]     = make_float2(v0, v1);
      *(float2*)&C[(size_t)(r0+8)*N + col] = make_float2(v2, v3);
    }
  }
}

// ---------------- LayerNorm + ReLU (fp32 g_zx -> fp16 g_Ah) ----------------
__global__ __launch_bounds__(256) void ln_relu(
    const float* __restrict__ sc, const float* __restrict__ bi)
{
  int row = blockIdx.x*8 + (threadIdx.x >> 5), lane = threadIdx.x & 31;
  float v[16], s = 0.f, s2 = 0.f;
  const float* src = &g_zx[(size_t)row*512 + lane*16];
  #pragma unroll
  for (int q = 0; q < 4; q++){
    float4 f = *(const float4*)&src[q*4];
    v[q*4]=f.x; v[q*4+1]=f.y; v[q*4+2]=f.z; v[q*4+3]=f.w;
    s += f.x+f.y+f.z+f.w;
    s2 += f.x*f.x+f.y*f.y+f.z*f.z+f.w*f.w;
  }
  #pragma unroll
  for (int o = 16; o; o >>= 1){
    s  += __shfl_xor_sync(0xffffffffu, s,  o);
    s2 += __shfl_xor_sync(0xffffffffu, s2, o);
  }
  float mu = s*(1.f/512.f);
  float var = fmaxf(s2*(1.f/512.f) - mu*mu, 0.f);
  float rs = rsqrtf(var + 1e-6f);
  unsigned* dst = (unsigned*)&g_Ah[(size_t)row*512 + lane*16];
  #pragma unroll
  for (int q = 0; q < 8; q++){
    int col = lane*16 + q*2;
    float y0 = fmaxf((v[q*2]  -mu)*rs*sc[col]   + bi[col],   0.f);
    float y1 = fmaxf((v[q*2+1]-mu)*rs*sc[col+1] + bi[col+1], 0.f);
    dst[q] = __half_as_ushort(__float2half(y0)) |
             ((unsigned)__half_as_ushort(__float2half(y1)) << 16);
  }
}

// ---------------- persistent LSTM layer: 256 CTAs, 2/SM -------------------
// smem: Bs 256x64 u32 (64KB) | As 64x64 u32 (16KB) | Zs 4x16x64 f32 (16KB)
#define RECSMEM ((256*64 + 64*64)*4 + 4*16*64*4)

__global__ __launch_bounds__(256,2) void rec_lstm(
    int L, const float* __restrict__ carryC,
    float* __restrict__ emb, float* __restrict__ coutP, float* __restrict__ houtP)
{
  extern __shared__ unsigned smu[];
  unsigned* Bs2 = smu;                 // [256][64] half2, swizzled
  unsigned* As2 = smu + 256*64;        // [64][64] half2, swizzled (16 rows)
  float* Zs = (float*)(smu + 320*64);  // [4][16][64]

  const unsigned* WhpU = g_WhpU[L];
  const int tid = threadIdx.x, cta = blockIdx.x;
  const int mg = cta >> 5, mbase = mg*16, ni = cta & 31;
  const int wid = tid >> 5, lane = tid & 31, gID = lane >> 2, tig = lane & 3;
  const int wN = wid & 1, wK = wid >> 1;

  for (int idx = tid; idx < 256*16; idx += 256){
    int r = idx >> 4, j4 = (idx & 15)*4;
    *(uint4*)&Bs2[r*64 + (j4 ^ ((r & 7) << 2))] =
      *(const uint4*)&WhpU[((size_t)ni*256 + r)*64 + j4];
  }
  const int er = tid >> 4, ec = tid & 15;
  float cst = carryC[(size_t)(mbase+er)*512 + ni*16 + ec];
  float nh_last = 0.f;

  int baseA[2], sA[2], baseB[4], sB[4];
  #pragma unroll
  for (int q = 0; q < 2; q++){
    int ra = (q*8 + gID)*4 + tig;
    baseA[q] = ra*64; sA[q] = (ra & 7) << 2;
  }
  #pragma unroll
  for (int q = 0; q < 4; q++){
    int rb = (wN*32 + q*8 + gID)*4 + tig;
    baseB[q] = rb*64; sB[q] = (rb & 7) << 2;
  }

  for (int t = 0; t < TT; t++){
    const unsigned* hb = g_hbufU[t & 1];
    __half* hn = (__half*)g_hbufU[(t & 1) ^ 1];

    #pragma unroll
    for (int i = 0; i < 4; i++){
      int idx = tid + i*256;
      int r = idx >> 4, j4 = (idx & 15)*4;
      cpa16(&As2[r*64 + (j4 ^ ((r & 7) << 2))], &hb[(mbase*4 + r)*64 + j4]);
    }
    asm volatile("cp.async.commit_group;" ::: "memory");

    float pz[4]; int rc, rn;
    {
      const float* zxr = &g_zx[((size_t)t*128 + mbase + er)*NZ + ni*16 + ec];
      pz[0] = __ldg(zxr);
      pz[1] = __ldg(zxr + 512);
      pz[2] = __ldg(zxr + 1024);
      pz[3] = __ldg(zxr + 1536);
      rc = g_rst[t*128 + mbase + er];
      rn = (t == TT-1) ? 0 : g_rst[(t+1)*128 + mbase + er];
    }
    asm volatile("cp.async.wait_group 0;" ::: "memory");
    __syncthreads();

    {
      float acc[4][4];
      #pragma unroll
      for (int nb = 0; nb < 4; nb++)
        #pragma unroll
        for (int q = 0; q < 4; q++) acc[nb][q] = 0.f;

      #pragma unroll
      for (int jj = 0; jj < 16; jj += 4){
        int j = wK*16 + jj;
        uint4 av[2], bv[4];
        #pragma unroll
        for (int q = 0; q < 2; q++)
          av[q] = *(const uint4*)&As2[baseA[q] + (j ^ sA[q])];
        #pragma unroll
        for (int q = 0; q < 4; q++)
          bv[q] = *(const uint4*)&Bs2[baseB[q] + (j ^ sB[q])];
        unsigned Alo[4] = {av[0].x, av[1].x, av[0].y, av[1].y};
        unsigned Ahi[4] = {av[0].z, av[1].z, av[0].w, av[1].w};
        #pragma unroll
        for (int nb = 0; nb < 4; nb++){
          unsigned Blo[2] = {bv[nb].x, bv[nb].y};
          mma16(acc[nb], Alo, Blo);
          unsigned Bhi[2] = {bv[nb].z, bv[nb].w};
          mma16(acc[nb], Ahi, Bhi);
        }
      }
      float* z = Zs + wK*(16*64);
      int zr = gID;
      #pragma unroll
      for (int nb = 0; nb < 4; nb++){
        int zc = wN*32 + nb*8 + tig*2;
        z[zr*64 + zc]         = acc[nb][0];
        z[zr*64 + zc + 1]     = acc[nb][1];
        z[(zr+8)*64 + zc]     = acc[nb][2];
        z[(zr+8)*64 + zc + 1] = acc[nb][3];
      }
    }
    __syncthreads();

    size_t rg = (size_t)t*128 + mbase + er;
    int hcol = ni*16 + ec;
    float nh;
    {
      float zi = pz[0], zf = pz[1], zg = pz[2], zo = pz[3];
      #pragma unroll
      for (int k4 = 0; k4 < 4; k4++){
        const float* z = Zs + k4*(16*64) + er*64;
        zi += z[ec]; zf += z[16 + ec]; zg += z[32 + ec]; zo += z[48 + ec];
      }
      float cc = rc ? 0.f : cst;
      float ig = 1.f/(1.f + __expf(-zi));
      float fg = 1.f/(1.f + __expf(-zf));
      float og = 1.f/(1.f + __expf(-zo));
      cc = fg*cc + ig*tanhx(zg);
      nh = og*tanhx(cc);
      cst = cc;

      // critical-path store: next-step h (reset-masked)
      unsigned yu = (unsigned)__half_as_ushort(__float2half(nh));
      unsigned hu = rn ? 0u : yu;
      unsigned hhi = __shfl_down_sync(0xffffffffu, hu, 1);
      if ((ec & 1) == 0){
        int pp = hcol >> 1;
        unsigned* hd = (unsigned*)hn + (((mbase+er)*4 + (pp & 3))*64 + (pp >> 2));
        asm volatile("st.global.cg.u32 [%0], %1;" :: "l"(hd), "r"(hu | (hhi << 16)) : "memory");
      }
    }

    // ---- early barrier arrival (release), then non-critical stores ----
    unsigned g0 = 0; bool leader = false;
    if (t < TT-1){
      __syncthreads();   // all h stores issued before release
      if (tid == 0){
        asm volatile("ld.relaxed.gpu.global.u32 %0, [%1];"
                     : "=r"(g0) : "l"(&g_gen[mg]) : "memory");
        unsigned old;
        asm volatile("atom.add.release.gpu.global.u32 %0, [%1], %2;"
                     : "=r"(old) : "l"(&g_cnt[mg]), "r"(1u) : "memory");
        if (old == 31u){
          asm volatile("st.relaxed.gpu.global.u32 [%0], %1;"
                       :: "l"(&g_cnt[mg]), "r"(0u) : "memory");
          __threadfence();
          asm volatile("red.release.gpu.global.add.u32 [%0], %1;"
                       :: "l"(&g_gen[mg]), "r"(1u) : "memory");
          leader = true;
        }
      }
    }

    // non-critical stores overlap the poll window
    {
      unsigned yu = (unsigned)__half_as_ushort(__float2half(nh));
      unsigned yhi = __shfl_down_sync(0xffffffffu, yu, 1);
      if ((ec & 1) == 0){
        unsigned* yd = (unsigned*)g_Ah + ((rg*512 + hcol) >> 1);
        asm volatile("st.global.cg.u32 [%0], %1;" :: "l"(yd), "r"(yu | (yhi << 16)) : "memory");
      }
      if (emb) emb[rg*512 + hcol] = nh;
    }
    nh_last = nh;

    if (t < TT-1){
      if (tid == 0 && !leader){
        unsigned g;
        do {
          asm volatile("ld.acquire.gpu.global.u32 %0, [%1];"
                       : "=r"(g) : "l"(&g_gen[mg]) : "memory");
        } while (g == g0);
      }
      __syncthreads();
    }
  }

  // tail: final carries
  coutP[(size_t)(mbase+er)*512 + ni*16 + ec] = cst;
  houtP[(size_t)(mbase+er)*512 + ni*16 + ec] = nh_last;
}

// ---------------- logits ----------------
__global__ __launch_bounds__(256) void logits_k(
    const float* __restrict__ W, const float* __restrict__ b, float* __restrict__ C)
{
  __shared__ float Ws[512*20];
  int tid = threadIdx.x;
  for (int i = tid; i < 512*20; i += 256) Ws[i] = W[i];
  __syncthreads();
  int row = blockIdx.x*8 + (tid >> 5), lane = tid & 31;
  float acc[20];
  #pragma unroll
  for (int c = 0; c < 20; c++) acc[c] = 0.f;
  #pragma unroll 4
  for (int j = 0; j < 16; j++){
    float a = g_hpre[(size_t)row*512 + lane + j*32];
    const float* w = &Ws[(lane + j*32)*20];
    #pragma unroll
    for (int c = 0; c < 20; c++) acc[c] += a*w[c];
  }
  #pragma unroll
  for (int c = 0; c < 20; c++)
    #pragma unroll
    for (int o = 16; o; o >>= 1) acc[c] += __shfl_xor_sync(0xffffffffu, acc[c], o);
  if (lane < 20) C[(size_t)row*20 + lane] = acc[lane] + b[lane];
}

// ---------------- launcher ----------------
extern "C" void kernel_launch(void* const* d_in, const int*, int, void* d_out_, int){
  const float* x     = (const float*)d_in[0];
  const void*  rsts  = d_in[1];
  const float* cc    = (const float*)d_in[2];
  const float* ch    = (const float*)d_in[3];
  const float* preW  = (const float*)d_in[4];
  const float* preb  = (const float*)d_in[5];
  const float* lns   = (const float*)d_in[6];
  const float* lnb   = (const float*)d_in[7];
  const float* Wi0   = (const float*)d_in[8];
  const float* Wh0   = (const float*)d_in[9];
  const float* b0    = (const float*)d_in[10];
  const float* Wi1   = (const float*)d_in[11];
  const float* Wh1   = (const float*)d_in[12];
  const float* b1    = (const float*)d_in[13];
  const float* postW = (const float*)d_in[14];
  const float* postb = (const float*)d_in[15];
  const float* outW  = (const float*)d_in[16];
  const float* outb  = (const float*)d_in[17];
  float* out = (float*)d_out_;
  const size_t OC = 0, OH = 131072, OL = 262144, OE = 1572864;

  cudaFuncSetAttribute(gemm_h<false>, cudaFuncAttributeMaxDynamicSharedMemorySize, GEMM_SMEM);
  cudaFuncSetAttribute(gemm_h<true>,  cudaFuncAttributeMaxDynamicSharedMemorySize, GEMM_SMEM);
  cudaFuncSetAttribute(rec_lstm, cudaFuncAttributeMaxDynamicSharedMemorySize, RECSMEM);

  detect_resets<<<1,256>>>((const unsigned char*)rsts);
  conv_resets<<<256,256>>>(rsts);
  dim3 g512(4,512), g2048(16,512);
  dim3 tp512(16,16), tp2048(64,16);

  conv_x<<<32768,256>>>(x, (size_t)TB*HH/4);
  pack_bh<<<tp512,256>>>(preW, 512);
  gemm_h<false><<<g512,256,GEMM_SMEM>>>(preb, 0, 512);
  ln_relu<<<8192,256>>>(lns, lnb);

  pack_bh<<<tp2048,256>>>(Wi0, 2048);
  gemm_h<false><<<g2048,256,GEMM_SMEM>>>(b0, 0, 2048);
  pack_wh<<<2048,512>>>(Wh0, 0);
  init_rec<<<256,256>>>(ch);
  rec_lstm<<<256,256,RECSMEM>>>(0, cc, nullptr, out + OC, out + OH);

  pack_bh<<<tp2048,256>>>(Wi1, 2048);
  gemm_h<false><<<g2048,256,GEMM_SMEM>>>(b1, 0, 2048);
  pack_wh<<<2048,512>>>(Wh1, 1);
  init_rec<<<256,256>>>(ch + 65536);
  rec_lstm<<<256,256,RECSMEM>>>(1, cc + 65536, out + OE,
                                out + OC + 65536, out + OH + 65536);

  pack_bh<<<tp512,256>>>(postW, 512);
  gemm_h<true><<<g512,256,GEMM_SMEM>>>(postb, 1, 512);
  logits_k<<<8192,256>>>(outW, outb, out + OL);
}

// round 14
// speedup vs baseline: 1.4388x; 1.4388x over previous
#include <cuda_runtime.h>
#include <cuda_fp16.h>
#include <math.h>

#define TT 512
#define BB 128
#define HH 512
#define NZ 2048
#define TB 65536

// ---------------- static device scratch ----------------
__device__ float g_zx[(size_t)TB*NZ];
__device__ float g_hpre[(size_t)TB*HH];
__device__ __half g_Ah[(size_t)TB*HH];           // fp16 GEMM A staging (reused)
__device__ __half g_wBh[2048*512];               // fp16 GEMM B, [n][k]
__device__ unsigned g_WhpU[2][(size_t)NZ*HH/2];  // half2: [(nc*4+p%4)*64 + p/4]
__device__ unsigned g_hbufU[2][BB*HH/2];         // half2: [(row*4+p%4)*64 + p/4]
__device__ unsigned char g_rst[TB];
__device__ unsigned g_cnt[8], g_gen[8];
__device__ int g_rmode;

__device__ __forceinline__ void mma16(float* c, const unsigned* a, const unsigned* b){
  asm volatile("mma.sync.aligned.m16n8k16.row.col.f32.f16.f16.f32 "
    "{%0,%1,%2,%3},{%4,%5,%6,%7},{%8,%9},{%0,%1,%2,%3};"
    : "+f"(c[0]),"+f"(c[1]),"+f"(c[2]),"+f"(c[3])
    : "r"(a[0]),"r"(a[1]),"r"(a[2]),"r"(a[3]),"r"(b[0]),"r"(b[1]));
}
__device__ __forceinline__ void cpa16(void* dst, const void* src){
  unsigned d = (unsigned)__cvta_generic_to_shared(dst);
  asm volatile("cp.async.cg.shared.global [%0], [%1], 16;" :: "r"(d), "l"(src));
}
__device__ __forceinline__ float tanhx(float x){
  return 1.f - __fdividef(2.f, __expf(2.f*x) + 1.f);
}

// ---------------- resets dtype detect + convert ----------------
__global__ void detect_resets(const unsigned char* p){
  __shared__ int cF, c1;
  if (threadIdx.x == 0){ cF = 0; c1 = 0; }
  __syncthreads();
  for (int i = threadIdx.x; i < 65536; i += 256){
    unsigned char v = p[i];
    if (v == 0x3f || v == 0x80) atomicAdd(&cF, 1);
    else if (v == 1 && (i & 3)) atomicAdd(&c1, 1);
  }
  __syncthreads();
  if (threadIdx.x == 0) g_rmode = cF ? 2 : (c1 ? 1 : 0);
}
__global__ void conv_resets(const void* p){
  int i = blockIdx.x*blockDim.x + threadIdx.x;
  int m = g_rmode;
  bool z;
  if (m == 1)      z = ((const unsigned char*)p)[i] != 0;
  else if (m == 2) z = ((const float*)p)[i] != 0.f;
  else             z = ((const int*)p)[i] != 0;
  g_rst[i] = z ? 1 : 0;
}

// ---------------- fp32 -> fp16 A staging ----------------
__global__ void conv_x(const float* __restrict__ X, size_t n4){
  size_t i = (size_t)blockIdx.x*blockDim.x + threadIdx.x;
  if (i < n4){
    float4 v = *(const float4*)&X[i*4];
    unsigned lo = __half_as_ushort(__float2half(v.x)) |
                  ((unsigned)__half_as_ushort(__float2half(v.y)) << 16);
    unsigned hi = __half_as_ushort(__float2half(v.z)) |
                  ((unsigned)__half_as_ushort(__float2half(v.w)) << 16);
    ((uint2*)g_Ah)[i] = make_uint2(lo, hi);
  }
}

// ---------------- B transpose+convert: [k][N] f32 -> [n][512] f16 ----------
__global__ void pack_bh(const float* __restrict__ B, int N){
  __shared__ float t[32][33];
  int bx = blockIdx.x*32, by = blockIdx.y*32;
  int lx = threadIdx.x & 31, ly = threadIdx.x >> 5;
  #pragma unroll
  for (int q = 0; q < 32; q += 8)
    t[ly+q][lx] = B[(size_t)(by+ly+q)*N + bx+lx];
  __syncthreads();
  #pragma unroll
  for (int q = 0; q < 32; q += 8)
    g_wBh[(size_t)(bx+ly+q)*512 + by+lx] = __float2half(t[lx][ly+q]);
}

// pack Wh[512][2048] -> fp16 pair-packed layout
__global__ void pack_wh(const float* __restrict__ Wh, int L){
  __half* dst = (__half*)g_WhpU[L];
  for (size_t idx = blockIdx.x*blockDim.x + threadIdx.x; idx < (size_t)HH*NZ;
       idx += (size_t)gridDim.x*blockDim.x){
    int k = idx >> 11, j = idx & (NZ-1);
    int g = j >> 9, r = j & 511;
    int nc = ((r >> 4) << 6) + (g << 4) + (r & 15);
    int p = k >> 1;
    dst[(((size_t)nc*4 + (p & 3))*64 + (p >> 2))*2 + (k & 1)] = __float2half(Wh[idx]);
  }
}

// init h buffer (fp16) with reset for t=0 pre-applied + counters
__global__ void init_rec(const float* __restrict__ carryH){
  int i = blockIdx.x*blockDim.x + threadIdx.x;
  if (i < BB*HH){
    int row = i >> 9, col = i & 511;
    float v = g_rst[row] ? 0.f : carryH[i];
    int p = col >> 1;
    ((__half*)g_hbufU[0])[((row*4 + (p & 3))*64 + (p >> 2))*2 + (col & 1)] = __float2half(v);
  }
  if (i < 8){ g_cnt[i] = 0u; g_gen[i] = 0u; }
}

// ---------------- bulk fp16 GEMM (4-stage cp.async) ----------------
#define GS 20
#define NSTG 4
#define GEMM_SMEM (2*NSTG*128*GS*4)
#define HA(st,r,p) shA[((st)*128+(r))*GS + (p)]
#define HB(st,n,p) shB[((st)*128+(n))*GS + (p)]

template<bool RELU>
__global__ __launch_bounds__(256,2) void gemm_h(
    const float* __restrict__ bias, int cSel, int N)
{
  extern __shared__ unsigned shu[];
  unsigned* shA = shu;
  unsigned* shB = shu + NSTG*128*GS;
  float* C = (cSel == 1) ? g_hpre : g_zx;
  const int mt = blockIdx.y, nt = blockIdx.x, tid = threadIdx.x;
  const int wid = tid >> 5, lane = tid & 31, gID = lane >> 2, tig = lane & 3;
  const int wM = wid >> 1, wN = wid & 1;

  float acc[2][8][4];
  #pragma unroll
  for (int mi = 0; mi < 2; mi++)
    #pragma unroll
    for (int ni = 0; ni < 8; ni++)
      #pragma unroll
      for (int q = 0; q < 4; q++) acc[mi][ni][q] = 0.f;

  auto issue = [&](int kt, int st){
    #pragma unroll
    for (int i = 0; i < 2; i++){
      int c = tid + i*256, r = c >> 2, po = c & 3;
      cpa16(&HA(st, r, po*4), &g_Ah[(size_t)(mt*128 + r)*512 + kt*32 + po*8]);
    }
    #pragma unroll
    for (int i = 0; i < 2; i++){
      int c = tid + i*256, n = c >> 2, po = c & 3;
      cpa16(&HB(st, n, po*4), &g_wBh[(size_t)(nt*128 + n)*512 + kt*32 + po*8]);
    }
    asm volatile("cp.async.commit_group;" ::: "memory");
  };

  issue(0, 0); issue(1, 1); issue(2, 2); issue(3, 3);
  int st = 0;
  for (int kt = 0; kt < 16; kt++){
    if (kt <= 12)      asm volatile("cp.async.wait_group 3;" ::: "memory");
    else if (kt == 13) asm volatile("cp.async.wait_group 2;" ::: "memory");
    else if (kt == 14) asm volatile("cp.async.wait_group 1;" ::: "memory");
    else               asm volatile("cp.async.wait_group 0;" ::: "memory");
    __syncthreads();
    #pragma unroll
    for (int kk = 0; kk < 2; kk++){
      int off = kk*8;
      unsigned a[2][4], b[8][2];
      #pragma unroll
      for (int mi = 0; mi < 2; mi++){
        int r0 = wM*32 + mi*16 + gID;
        a[mi][0] = HA(st, r0,   tig + off);
        a[mi][1] = HA(st, r0+8, tig + off);
        a[mi][2] = HA(st, r0,   tig + 4 + off);
        a[mi][3] = HA(st, r0+8, tig + 4 + off);
      }
      #pragma unroll
      for (int ni = 0; ni < 8; ni++){
        int n0 = wN*64 + ni*8 + gID;
        b[ni][0] = HB(st, n0, tig + off);
        b[ni][1] = HB(st, n0, tig + 4 + off);
      }
      #pragma unroll
      for (int mi = 0; mi < 2; mi++)
        #pragma unroll
        for (int ni = 0; ni < 8; ni++)
          mma16(acc[mi][ni], a[mi], b[ni]);
    }
    __syncthreads();
    if (kt + NSTG < 16) issue(kt + NSTG, st);
    st = (st == NSTG-1) ? 0 : st + 1;
  }

  #pragma unroll
  for (int mi = 0; mi < 2; mi++){
    int r0 = mt*128 + wM*32 + mi*16 + gID;
    #pragma unroll
    for (int ni = 0; ni < 8; ni++){
      int col = nt*128 + wN*64 + ni*8 + tig*2;
      float b0 = bias[col], b1 = bias[col+1];
      float v0 = acc[mi][ni][0]+b0, v1 = acc[mi][ni][1]+b1;
      float v2 = acc[mi][ni][2]+b0, v3 = acc[mi][ni][3]+b1;
      if (RELU){ v0=fmaxf(v0,0.f); v1=fmaxf(v1,0.f); v2=fmaxf(v2,0.f); v3=fmaxf(v3,0.f); }
      *(float2*)&C[(size_t)r0*N + col]     = make_float2(v0, v1);
      *(float2*)&C[(size_t)(r0+8)*N + col] = make_float2(v2, v3);
    }
  }
}

// ---------------- LayerNorm + ReLU (fp32 g_zx -> fp16 g_Ah) ----------------
__global__ __launch_bounds__(256) void ln_relu(
    const float* __restrict__ sc, const float* __restrict__ bi)
{
  int row = blockIdx.x*8 + (threadIdx.x >> 5), lane = threadIdx.x & 31;
  float v[16], s = 0.f, s2 = 0.f;
  const float* src = &g_zx[(size_t)row*512 + lane*16];
  #pragma unroll
  for (int q = 0; q < 4; q++){
    float4 f = *(const float4*)&src[q*4];
    v[q*4]=f.x; v[q*4+1]=f.y; v[q*4+2]=f.z; v[q*4+3]=f.w;
    s += f.x+f.y+f.z+f.w;
    s2 += f.x*f.x+f.y*f.y+f.z*f.z+f.w*f.w;
  }
  #pragma unroll
  for (int o = 16; o; o >>= 1){
    s  += __shfl_xor_sync(0xffffffffu, s,  o);
    s2 += __shfl_xor_sync(0xffffffffu, s2, o);
  }
  float mu = s*(1.f/512.f);
  float var = fmaxf(s2*(1.f/512.f) - mu*mu, 0.f);
  float rs = rsqrtf(var + 1e-6f);
  unsigned* dst = (unsigned*)&g_Ah[(size_t)row*512 + lane*16];
  #pragma unroll
  for (int q = 0; q < 8; q++){
    int col = lane*16 + q*2;
    float y0 = fmaxf((v[q*2]  -mu)*rs*sc[col]   + bi[col],   0.f);
    float y1 = fmaxf((v[q*2+1]-mu)*rs*sc[col+1] + bi[col+1], 0.f);
    dst[q] = __half_as_ushort(__float2half(y0)) |
             ((unsigned)__half_as_ushort(__float2half(y1)) << 16);
  }
}

// ---------------- persistent LSTM layer: 256 CTAs, 2/SM -------------------
// smem: Bs 256x64 u32 (64KB) | As 64x64 u32 (16KB) | Zs 4x16x64 f32 (16KB)
#define RECSMEM ((256*64 + 64*64)*4 + 4*16*64*4)

__device__ __forceinline__ void gbar(int mg){
  __syncthreads();
  if (threadIdx.x == 0){
    unsigned g0;
    asm volatile("ld.relaxed.gpu.global.u32 %0, [%1];"
                 : "=r"(g0) : "l"(&g_gen[mg]) : "memory");
    unsigned old;
    asm volatile("atom.add.release.gpu.global.u32 %0, [%1], %2;"
                 : "=r"(old) : "l"(&g_cnt[mg]), "r"(1u) : "memory");
    if (old == 31u){
      asm volatile("st.relaxed.gpu.global.u32 [%0], %1;"
                   :: "l"(&g_cnt[mg]), "r"(0u) : "memory");
      __threadfence();
      asm volatile("red.release.gpu.global.add.u32 [%0], %1;"
                   :: "l"(&g_gen[mg]), "r"(1u) : "memory");
    } else {
      unsigned g;
      do {
        asm volatile("ld.acquire.gpu.global.u32 %0, [%1];"
                     : "=r"(g) : "l"(&g_gen[mg]) : "memory");
      } while (g == g0);
    }
  }
  __syncthreads();
}

__global__ __launch_bounds__(256,2) void rec_lstm(
    int L, const float* __restrict__ carryC,
    float* __restrict__ emb, float* __restrict__ coutP, float* __restrict__ houtP)
{
  extern __shared__ unsigned smu[];
  unsigned* Bs2 = smu;                 // [256][64] half2, swizzled
  unsigned* As2 = smu + 256*64;        // [64][64] half2, swizzled (16 rows)
  float* Zs = (float*)(smu + 320*64);  // [4][16][64]

  const unsigned* WhpU = g_WhpU[L];
  const int tid = threadIdx.x, cta = blockIdx.x;
  const int mg = cta >> 5, mbase = mg*16, ni = cta & 31;
  const int wid = tid >> 5, lane = tid & 31, gID = lane >> 2, tig = lane & 3;
  const int wN = wid & 1, wK = wid >> 1;

  // resident Wh slice: 256 sub-rows x 64 uints
  for (int idx = tid; idx < 256*16; idx += 256){
    int r = idx >> 4, j4 = (idx & 15)*4;
    *(uint4*)&Bs2[r*64 + (j4 ^ ((r & 7) << 2))] =
      *(const uint4*)&WhpU[((size_t)ni*256 + r)*64 + j4];
  }
  // one gate element per thread
  const int er = tid >> 4, ec = tid & 15;
  float cst = carryC[(size_t)(mbase+er)*512 + ni*16 + ec];

  int baseA[2], sA[2], baseB[4], sB[4];
  #pragma unroll
  for (int q = 0; q < 2; q++){
    int ra = (q*8 + gID)*4 + tig;
    baseA[q] = ra*64; sA[q] = (ra & 7) << 2;
  }
  #pragma unroll
  for (int q = 0; q < 4; q++){
    int rb = (wN*32 + q*8 + gID)*4 + tig;
    baseB[q] = rb*64; sB[q] = (rb & 7) << 2;
  }

  for (int t = 0; t < TT; t++){
    const unsigned* hb = g_hbufU[t & 1];
    __half* hn = (__half*)g_hbufU[(t & 1) ^ 1];

    // As fill: 16 rows = 64 sub-rows x 16 uint4
    #pragma unroll
    for (int i = 0; i < 4; i++){
      int idx = tid + i*256;
      int r = idx >> 4, j4 = (idx & 15)*4;
      cpa16(&As2[r*64 + (j4 ^ ((r & 7) << 2))], &hb[(mbase*4 + r)*64 + j4]);
    }
    asm volatile("cp.async.commit_group;" ::: "memory");

    // prefetch Zx + resets (overlaps cp.async)
    float pz[4]; int rc, rn;
    {
      const float* zxr = &g_zx[((size_t)t*128 + mbase + er)*NZ + ni*16 + ec];
      pz[0] = __ldg(zxr);
      pz[1] = __ldg(zxr + 512);
      pz[2] = __ldg(zxr + 1024);
      pz[3] = __ldg(zxr + 1536);
      rc = g_rst[t*128 + mbase + er];
      rn = (t == TT-1) ? 0 : g_rst[(t+1)*128 + mbase + er];
    }
    asm volatile("cp.async.wait_group 0;" ::: "memory");
    __syncthreads();

    {
      float acc[4][4];
      #pragma unroll
      for (int nb = 0; nb < 4; nb++)
        #pragma unroll
        for (int q = 0; q < 4; q++) acc[nb][q] = 0.f;

      #pragma unroll
      for (int jj = 0; jj < 16; jj += 4){
        int j = wK*16 + jj;
        uint4 av[2], bv[4];
        #pragma unroll
        for (int q = 0; q < 2; q++)
          av[q] = *(const uint4*)&As2[baseA[q] + (j ^ sA[q])];
        #pragma unroll
        for (int q = 0; q < 4; q++)
          bv[q] = *(const uint4*)&Bs2[baseB[q] + (j ^ sB[q])];
        unsigned Alo[4] = {av[0].x, av[1].x, av[0].y, av[1].y};
        unsigned Ahi[4] = {av[0].z, av[1].z, av[0].w, av[1].w};
        #pragma unroll
        for (int nb = 0; nb < 4; nb++){
          unsigned Blo[2] = {bv[nb].x, bv[nb].y};
          mma16(acc[nb], Alo, Blo);
          unsigned Bhi[2] = {bv[nb].z, bv[nb].w};
          mma16(acc[nb], Ahi, Bhi);
        }
      }
      float* z = Zs + wK*(16*64);
      int zr = gID;
      #pragma unroll
      for (int nb = 0; nb < 4; nb++){
        int zc = wN*32 + nb*8 + tig*2;
        z[zr*64 + zc]         = acc[nb][0];
        z[zr*64 + zc + 1]     = acc[nb][1];
        z[(zr+8)*64 + zc]     = acc[nb][2];
        z[(zr+8)*64 + zc + 1] = acc[nb][3];
      }
    }
    __syncthreads();

    {
      size_t rg = (size_t)t*128 + mbase + er;
      float zi = pz[0], zf = pz[1], zg = pz[2], zo = pz[3];
      #pragma unroll
      for (int k4 = 0; k4 < 4; k4++){
        const float* z = Zs + k4*(16*64) + er*64;
        zi += z[ec]; zf += z[16 + ec]; zg += z[32 + ec]; zo += z[48 + ec];
      }
      float cc = rc ? 0.f : cst;
      float ig = 1.f/(1.f + __expf(-zi));
      float fg = 1.f/(1.f + __expf(-zf));
      float og = 1.f/(1.f + __expf(-zo));
      cc = fg*cc + ig*tanhx(zg);
      float nh = og*tanhx(cc);
      cst = cc;
      int hcol = ni*16 + ec;

      unsigned yu = (unsigned)__half_as_ushort(__float2half(nh));
      unsigned yhi = __shfl_down_sync(0xffffffffu, yu, 1);
      unsigned hu = rn ? 0u : yu;
      unsigned hhi = __shfl_down_sync(0xffffffffu, hu, 1);
      if ((ec & 1) == 0){
        int pp = hcol >> 1;
        unsigned* hd = (unsigned*)hn + (((mbase+er)*4 + (pp & 3))*64 + (pp >> 2));
        asm volatile("st.global.cg.u32 [%0], %1;" :: "l"(hd), "r"(hu | (hhi << 16)) : "memory");
        unsigned* yd = (unsigned*)g_Ah + ((rg*512 + hcol) >> 1);
        asm volatile("st.global.cg.u32 [%0], %1;" :: "l"(yd), "r"(yu | (yhi << 16)) : "memory");
      }
      if (emb) emb[rg*512 + hcol] = nh;
      if (t == TT-1){
        coutP[(size_t)(mbase+er)*512 + hcol] = cc;
        houtP[(size_t)(mbase+er)*512 + hcol] = nh;
      }
    }
    gbar(mg);
  }
}

// ---------------- logits ----------------
__global__ __launch_bounds__(256) void logits_k(
    const float* __restrict__ W, const float* __restrict__ b, float* __restrict__ C)
{
  __shared__ float Ws[512*20];
  int tid = threadIdx.x;
  for (int i = tid; i < 512*20; i += 256) Ws[i] = W[i];
  __syncthreads();
  int row = blockIdx.x*8 + (tid >> 5), lane = tid & 31;
  float acc[20];
  #pragma unroll
  for (int c = 0; c < 20; c++) acc[c] = 0.f;
  #pragma unroll 4
  for (int j = 0; j < 16; j++){
    float a = g_hpre[(size_t)row*512 + lane + j*32];
    const float* w = &Ws[(lane + j*32)*20];
    #pragma unroll
    for (int c = 0; c < 20; c++) acc[c] += a*w[c];
  }
  #pragma unroll
  for (int c = 0; c < 20; c++)
    #pragma unroll
    for (int o = 16; o; o >>= 1) acc[c] += __shfl_xor_sync(0xffffffffu, acc[c], o);
  if (lane < 20) C[(size_t)row*20 + lane] = acc[lane] + b[lane];
}

// ---------------- launcher ----------------
extern "C" void kernel_launch(void* const* d_in, const int*, int, void* d_out_, int){
  const float* x     = (const float*)d_in[0];
  const void*  rsts  = d_in[1];
  const float* cc    = (const float*)d_in[2];
  const float* ch    = (const float*)d_in[3];
  const float* preW  = (const float*)d_in[4];
  const float* preb  = (const float*)d_in[5];
  const float* lns   = (const float*)d_in[6];
  const float* lnb   = (const float*)d_in[7];
  const float* Wi0   = (const float*)d_in[8];
  const float* Wh0   = (const float*)d_in[9];
  const float* b0    = (const float*)d_in[10];
  const float* Wi1   = (const float*)d_in[11];
  const float* Wh1   = (const float*)d_in[12];
  const float* b1    = (const float*)d_in[13];
  const float* postW = (const float*)d_in[14];
  const float* postb = (const float*)d_in[15];
  const float* outW  = (const float*)d_in[16];
  const float* outb  = (const float*)d_in[17];
  float* out = (float*)d_out_;
  const size_t OC = 0, OH = 131072, OL = 262144, OE = 1572864;

  cudaFuncSetAttribute(gemm_h<false>, cudaFuncAttributeMaxDynamicSharedMemorySize, GEMM_SMEM);
  cudaFuncSetAttribute(gemm_h<true>,  cudaFuncAttributeMaxDynamicSharedMemorySize, GEMM_SMEM);
  cudaFuncSetAttribute(rec_lstm, cudaFuncAttributeMaxDynamicSharedMemorySize, RECSMEM);

  detect_resets<<<1,256>>>((const unsigned char*)rsts);
  conv_resets<<<256,256>>>(rsts);
  dim3 g512(4,512), g2048(16,512);
  dim3 tp512(16,16), tp2048(64,16);

  conv_x<<<32768,256>>>(x, (size_t)TB*HH/4);
  pack_bh<<<tp512,256>>>(preW, 512);
  gemm_h<false><<<g512,256,GEMM_SMEM>>>(preb, 0, 512);
  ln_relu<<<8192,256>>>(lns, lnb);

  pack_bh<<<tp2048,256>>>(Wi0, 2048);
  gemm_h<false><<<g2048,256,GEMM_SMEM>>>(b0, 0, 2048);
  pack_wh<<<2048,512>>>(Wh0, 0);
  init_rec<<<256,256>>>(ch);
  rec_lstm<<<256,256,RECSMEM>>>(0, cc, nullptr, out + OC, out + OH);

  pack_bh<<<tp2048,256>>>(Wi1, 2048);
  gemm_h<false><<<g2048,256,GEMM_SMEM>>>(b1, 0, 2048);
  pack_wh<<<2048,512>>>(Wh1, 1);
  init_rec<<<256,256>>>(ch + 65536);
  rec_lstm<<<256,256,RECSMEM>>>(1, cc + 65536, out + OE,
                                out + OC + 65536, out + OH + 65536);

  pack_bh<<<tp512,256>>>(postW, 512);
  gemm_h<true><<<g512,256,GEMM_SMEM>>>(postb, 1, 512);
  logits_k<<<8192,256>>>(outW, outb, out + OL);
}

// round 15
// speedup vs baseline: 1.6029x; 1.1141x over previous
#include <cuda_runtime.h>
#include <cuda_fp16.h>
#include <math.h>

#define TT 512
#define BB 128
#define HH 512
#define NZ 2048
#define TB 65536

// ---------------- static device scratch ----------------
__device__ float g_zx[(size_t)TB*NZ];
__device__ float g_hpre[(size_t)TB*HH];
__device__ __half g_Ah[(size_t)TB*HH];           // fp16 GEMM A staging (reused)
__device__ __half g_wBh[2048*512];               // fp16 GEMM B, [n][k]
__device__ unsigned g_WhpU[2][(size_t)NZ*HH/2];  // half2: [(nc*4+p%4)*64 + p/4]
__device__ unsigned g_hbufU[2][BB*HH/2];         // half2: [(row*4+p%4)*64 + p/4]
__device__ unsigned char g_rst[TB];
__device__ unsigned g_flag[8][32*32];            // per-CTA barrier flags, 128B stride
__device__ int g_rmode;

__device__ __forceinline__ void mma16(float* c, const unsigned* a, const unsigned* b){
  asm volatile("mma.sync.aligned.m16n8k16.row.col.f32.f16.f16.f32 "
    "{%0,%1,%2,%3},{%4,%5,%6,%7},{%8,%9},{%0,%1,%2,%3};"
    : "+f"(c[0]),"+f"(c[1]),"+f"(c[2]),"+f"(c[3])
    : "r"(a[0]),"r"(a[1]),"r"(a[2]),"r"(a[3]),"r"(b[0]),"r"(b[1]));
}
__device__ __forceinline__ void cpa16(void* dst, const void* src){
  unsigned d = (unsigned)__cvta_generic_to_shared(dst);
  asm volatile("cp.async.cg.shared.global [%0], [%1], 16;" :: "r"(d), "l"(src));
}
__device__ __forceinline__ float tanhx(float x){
  return 1.f - __fdividef(2.f, __expf(2.f*x) + 1.f);
}

// ---------------- resets dtype detect + convert ----------------
__global__ void detect_resets(const unsigned char* p){
  __shared__ int cF, c1;
  if (threadIdx.x == 0){ cF = 0; c1 = 0; }
  __syncthreads();
  for (int i = threadIdx.x; i < 65536; i += 256){
    unsigned char v = p[i];
    if (v == 0x3f || v == 0x80) atomicAdd(&cF, 1);
    else if (v == 1 && (i & 3)) atomicAdd(&c1, 1);
  }
  __syncthreads();
  if (threadIdx.x == 0) g_rmode = cF ? 2 : (c1 ? 1 : 0);
}
__global__ void conv_resets(const void* p){
  int i = blockIdx.x*blockDim.x + threadIdx.x;
  int m = g_rmode;
  bool z;
  if (m == 1)      z = ((const unsigned char*)p)[i] != 0;
  else if (m == 2) z = ((const float*)p)[i] != 0.f;
  else             z = ((const int*)p)[i] != 0;
  g_rst[i] = z ? 1 : 0;
}

// ---------------- fp32 -> fp16 A staging ----------------
__global__ void conv_x(const float* __restrict__ X, size_t n4){
  size_t i = (size_t)blockIdx.x*blockDim.x + threadIdx.x;
  if (i < n4){
    float4 v = *(const float4*)&X[i*4];
    unsigned lo = __half_as_ushort(__float2half(v.x)) |
                  ((unsigned)__half_as_ushort(__float2half(v.y)) << 16);
    unsigned hi = __half_as_ushort(__float2half(v.z)) |
                  ((unsigned)__half_as_ushort(__float2half(v.w)) << 16);
    ((uint2*)g_Ah)[i] = make_uint2(lo, hi);
  }
}

// ---------------- B transpose+convert: [k][N] f32 -> [n][512] f16 ----------
__global__ void pack_bh(const float* __restrict__ B, int N){
  __shared__ float t[32][33];
  int bx = blockIdx.x*32, by = blockIdx.y*32;
  int lx = threadIdx.x & 31, ly = threadIdx.x >> 5;
  #pragma unroll
  for (int q = 0; q < 32; q += 8)
    t[ly+q][lx] = B[(size_t)(by+ly+q)*N + bx+lx];
  __syncthreads();
  #pragma unroll
  for (int q = 0; q < 32; q += 8)
    g_wBh[(size_t)(bx+ly+q)*512 + by+lx] = __float2half(t[lx][ly+q]);
}

// pack Wh[512][2048] -> fp16 pair-packed layout
__global__ void pack_wh(const float* __restrict__ Wh, int L){
  __half* dst = (__half*)g_WhpU[L];
  for (size_t idx = blockIdx.x*blockDim.x + threadIdx.x; idx < (size_t)HH*NZ;
       idx += (size_t)gridDim.x*blockDim.x){
    int k = idx >> 11, j = idx & (NZ-1);
    int g = j >> 9, r = j & 511;
    int nc = ((r >> 4) << 6) + (g << 4) + (r & 15);
    int p = k >> 1;
    dst[(((size_t)nc*4 + (p & 3))*64 + (p >> 2))*2 + (k & 1)] = __float2half(Wh[idx]);
  }
}

// init h buffer (fp16) with reset for t=0 pre-applied + flags
__global__ void init_rec(const float* __restrict__ carryH){
  int i = blockIdx.x*blockDim.x + threadIdx.x;
  if (i < BB*HH){
    int row = i >> 9, col = i & 511;
    float v = g_rst[row] ? 0.f : carryH[i];
    int p = col >> 1;
    ((__half*)g_hbufU[0])[((row*4 + (p & 3))*64 + (p >> 2))*2 + (col & 1)] = __float2half(v);
  }
  if (i < 8*32*32) ((unsigned*)g_flag)[i] = 0u;
}

// ---------------- bulk fp16 GEMM (4-stage cp.async) ----------------
#define GS 20
#define NSTG 4
#define GEMM_SMEM (2*NSTG*128*GS*4)
#define HA(st,r,p) shA[((st)*128+(r))*GS + (p)]
#define HB(st,n,p) shB[((st)*128+(n))*GS + (p)]

template<bool RELU>
__global__ __launch_bounds__(256,2) void gemm_h(
    const float* __restrict__ bias, int cSel, int N)
{
  extern __shared__ unsigned shu[];
  unsigned* shA = shu;
  unsigned* shB = shu + NSTG*128*GS;
  float* C = (cSel == 1) ? g_hpre : g_zx;
  const int mt = blockIdx.y, nt = blockIdx.x, tid = threadIdx.x;
  const int wid = tid >> 5, lane = tid & 31, gID = lane >> 2, tig = lane & 3;
  const int wM = wid >> 1, wN = wid & 1;

  float acc[2][8][4];
  #pragma unroll
  for (int mi = 0; mi < 2; mi++)
    #pragma unroll
    for (int ni = 0; ni < 8; ni++)
      #pragma unroll
      for (int q = 0; q < 4; q++) acc[mi][ni][q] = 0.f;

  auto issue = [&](int kt, int st){
    #pragma unroll
    for (int i = 0; i < 2; i++){
      int c = tid + i*256, r = c >> 2, po = c & 3;
      cpa16(&HA(st, r, po*4), &g_Ah[(size_t)(mt*128 + r)*512 + kt*32 + po*8]);
    }
    #pragma unroll
    for (int i = 0; i < 2; i++){
      int c = tid + i*256, n = c >> 2, po = c & 3;
      cpa16(&HB(st, n, po*4), &g_wBh[(size_t)(nt*128 + n)*512 + kt*32 + po*8]);
    }
    asm volatile("cp.async.commit_group;" ::: "memory");
  };

  issue(0, 0); issue(1, 1); issue(2, 2); issue(3, 3);
  int st = 0;
  for (int kt = 0; kt < 16; kt++){
    if (kt <= 12)      asm volatile("cp.async.wait_group 3;" ::: "memory");
    else if (kt == 13) asm volatile("cp.async.wait_group 2;" ::: "memory");
    else if (kt == 14) asm volatile("cp.async.wait_group 1;" ::: "memory");
    else               asm volatile("cp.async.wait_group 0;" ::: "memory");
    __syncthreads();
    #pragma unroll
    for (int kk = 0; kk < 2; kk++){
      int off = kk*8;
      unsigned a[2][4], b[8][2];
      #pragma unroll
      for (int mi = 0; mi < 2; mi++){
        int r0 = wM*32 + mi*16 + gID;
        a[mi][0] = HA(st, r0,   tig + off);
        a[mi][1] = HA(st, r0+8, tig + off);
        a[mi][2] = HA(st, r0,   tig + 4 + off);
        a[mi][3] = HA(st, r0+8, tig + 4 + off);
      }
      #pragma unroll
      for (int ni = 0; ni < 8; ni++){
        int n0 = wN*64 + ni*8 + gID;
        b[ni][0] = HB(st, n0, tig + off);
        b[ni][1] = HB(st, n0, tig + 4 + off);
      }
      #pragma unroll
      for (int mi = 0; mi < 2; mi++)
        #pragma unroll
        for (int ni = 0; ni < 8; ni++)
          mma16(acc[mi][ni], a[mi], b[ni]);
    }
    __syncthreads();
    if (kt + NSTG < 16) issue(kt + NSTG, st);
    st = (st == NSTG-1) ? 0 : st + 1;
  }

  #pragma unroll
  for (int mi = 0; mi < 2; mi++){
    int r0 = mt*128 + wM*32 + mi*16 + gID;
    #pragma unroll
    for (int ni = 0; ni < 8; ni++){
      int col = nt*128 + wN*64 + ni*8 + tig*2;
      float b0 = bias[col], b1 = bias[col+1];
      float v0 = acc[mi][ni][0]+b0, v1 = acc[mi][ni][1]+b1;
      float v2 = acc[mi][ni][2]+b0, v3 = acc[mi][ni][3]+b1;
      if (RELU){ v0=fmaxf(v0,0.f); v1=fmaxf(v1,0.f); v2=fmaxf(v2,0.f); v3=fmaxf(v3,0.f); }
      *(float2*)&C[(size_t)r0*N + col]     = make_float2(v0, v1);
      *(float2*)&C[(size_t)(r0+8)*N + col] = make_float2(v2, v3);
    }
  }
}

// ---------------- LayerNorm + ReLU (fp32 g_zx -> fp16 g_Ah) ----------------
__global__ __launch_bounds__(256) void ln_relu(
    const float* __restrict__ sc, const float* __restrict__ bi)
{
  int row = blockIdx.x*8 + (threadIdx.x >> 5), lane = threadIdx.x & 31;
  float v[16], s = 0.f, s2 = 0.f;
  const float* src = &g_zx[(size_t)row*512 + lane*16];
  #pragma unroll
  for (int q = 0; q < 4; q++){
    float4 f = *(const float4*)&src[q*4];
    v[q*4]=f.x; v[q*4+1]=f.y; v[q*4+2]=f.z; v[q*4+3]=f.w;
    s += f.x+f.y+f.z+f.w;
    s2 += f.x*f.x+f.y*f.y+f.z*f.z+f.w*f.w;
  }
  #pragma unroll
  for (int o = 16; o; o >>= 1){
    s  += __shfl_xor_sync(0xffffffffu, s,  o);
    s2 += __shfl_xor_sync(0xffffffffu, s2, o);
  }
  float mu = s*(1.f/512.f);
  float var = fmaxf(s2*(1.f/512.f) - mu*mu, 0.f);
  float rs = rsqrtf(var + 1e-6f);
  unsigned* dst = (unsigned*)&g_Ah[(size_t)row*512 + lane*16];
  #pragma unroll
  for (int q = 0; q < 8; q++){
    int col = lane*16 + q*2;
    float y0 = fmaxf((v[q*2]  -mu)*rs*sc[col]   + bi[col],   0.f);
    float y1 = fmaxf((v[q*2+1]-mu)*rs*sc[col+1] + bi[col+1], 0.f);
    dst[q] = __half_as_ushort(__float2half(y0)) |
             ((unsigned)__half_as_ushort(__float2half(y1)) << 16);
  }
}

// ---------------- persistent LSTM layer: 256 CTAs, 2/SM -------------------
// smem: Bs 256x64 u32 (64KB) | As 64x64 u32 (16KB) | Zs 4x16x64 f32 (16KB)
#define RECSMEM ((256*64 + 64*64)*4 + 4*16*64*4)

// distributed flag barrier: arrive = 1 uncontended release store; wait =
// 32 threads poll the 32 group flags in parallel (monotonic value t+1).
__device__ __forceinline__ void gbar_flag(int mg, int cig, unsigned tgt){
  __syncthreads();
  if (threadIdx.x == 0){
    asm volatile("st.release.gpu.global.u32 [%0], %1;"
                 :: "l"(&g_flag[mg][cig*32]), "r"(tgt) : "memory");
  }
  if (threadIdx.x < 32){
    unsigned g;
    do {
      asm volatile("ld.acquire.gpu.global.u32 %0, [%1];"
                   : "=r"(g) : "l"(&g_flag[mg][threadIdx.x*32]) : "memory");
    } while (g < tgt);
  }
  __syncthreads();
}

__global__ __launch_bounds__(256,2) void rec_lstm(
    int L, const float* __restrict__ carryC,
    float* __restrict__ emb, float* __restrict__ coutP, float* __restrict__ houtP)
{
  extern __shared__ unsigned smu[];
  unsigned* Bs2 = smu;                 // [256][64] half2, swizzled
  unsigned* As2 = smu + 256*64;        // [64][64] half2, swizzled (16 rows)
  float* Zs = (float*)(smu + 320*64);  // [4][16][64]

  const unsigned* WhpU = g_WhpU[L];
  const int tid = threadIdx.x, cta = blockIdx.x;
  const int mg = cta >> 5, mbase = mg*16, ni = cta & 31;
  const int wid = tid >> 5, lane = tid & 31, gID = lane >> 2, tig = lane & 3;
  const int wN = wid & 1, wK = wid >> 1;

  // resident Wh slice: 256 sub-rows x 64 uints
  for (int idx = tid; idx < 256*16; idx += 256){
    int r = idx >> 4, j4 = (idx & 15)*4;
    *(uint4*)&Bs2[r*64 + (j4 ^ ((r & 7) << 2))] =
      *(const uint4*)&WhpU[((size_t)ni*256 + r)*64 + j4];
  }
  // one gate element per thread
  const int er = tid >> 4, ec = tid & 15;
  float cst = carryC[(size_t)(mbase+er)*512 + ni*16 + ec];

  int baseA[2], sA[2], baseB[4], sB[4];
  #pragma unroll
  for (int q = 0; q < 2; q++){
    int ra = (q*8 + gID)*4 + tig;
    baseA[q] = ra*64; sA[q] = (ra & 7) << 2;
  }
  #pragma unroll
  for (int q = 0; q < 4; q++){
    int rb = (wN*32 + q*8 + gID)*4 + tig;
    baseB[q] = rb*64; sB[q] = (rb & 7) << 2;
  }

  for (int t = 0; t < TT; t++){
    const unsigned* hb = g_hbufU[t & 1];
    __half* hn = (__half*)g_hbufU[(t & 1) ^ 1];

    // As fill: 16 rows = 64 sub-rows x 16 uint4
    #pragma unroll
    for (int i = 0; i < 4; i++){
      int idx = tid + i*256;
      int r = idx >> 4, j4 = (idx & 15)*4;
      cpa16(&As2[r*64 + (j4 ^ ((r & 7) << 2))], &hb[(mbase*4 + r)*64 + j4]);
    }
    asm volatile("cp.async.commit_group;" ::: "memory");

    // prefetch Zx + resets (overlaps cp.async)
    float pz[4]; int rc, rn;
    {
      const float* zxr = &g_zx[((size_t)t*128 + mbase + er)*NZ + ni*16 + ec];
      pz[0] = __ldg(zxr);
      pz[1] = __ldg(zxr + 512);
      pz[2] = __ldg(zxr + 1024);
      pz[3] = __ldg(zxr + 1536);
      rc = g_rst[t*128 + mbase + er];
      rn = (t == TT-1) ? 0 : g_rst[(t+1)*128 + mbase + er];
    }
    asm volatile("cp.async.wait_group 0;" ::: "memory");
    __syncthreads();

    {
      float acc[4][4];
      #pragma unroll
      for (int nb = 0; nb < 4; nb++)
        #pragma unroll
        for (int q = 0; q < 4; q++) acc[nb][q] = 0.f;

      #pragma unroll
      for (int jj = 0; jj < 16; jj += 4){
        int j = wK*16 + jj;
        uint4 av[2], bv[4];
        #pragma unroll
        for (int q = 0; q < 2; q++)
          av[q] = *(const uint4*)&As2[baseA[q] + (j ^ sA[q])];
        #pragma unroll
        for (int q = 0; q < 4; q++)
          bv[q] = *(const uint4*)&Bs2[baseB[q] + (j ^ sB[q])];
        unsigned Alo[4] = {av[0].x, av[1].x, av[0].y, av[1].y};
        unsigned Ahi[4] = {av[0].z, av[1].z, av[0].w, av[1].w};
        #pragma unroll
        for (int nb = 0; nb < 4; nb++){
          unsigned Blo[2] = {bv[nb].x, bv[nb].y};
          mma16(acc[nb], Alo, Blo);
          unsigned Bhi[2] = {bv[nb].z, bv[nb].w};
          mma16(acc[nb], Ahi, Bhi);
        }
      }
      float* z = Zs + wK*(16*64);
      int zr = gID;
      #pragma unroll
      for (int nb = 0; nb < 4; nb++){
        int zc = wN*32 + nb*8 + tig*2;
        z[zr*64 + zc]         = acc[nb][0];
        z[zr*64 + zc + 1]     = acc[nb][1];
        z[(zr+8)*64 + zc]     = acc[nb][2];
        z[(zr+8)*64 + zc + 1] = acc[nb][3];
      }
    }
    __syncthreads();

    {
      size_t rg = (size_t)t*128 + mbase + er;
      float zi = pz[0], zf = pz[1], zg = pz[2], zo = pz[3];
      #pragma unroll
      for (int k4 = 0; k4 < 4; k4++){
        const float* z = Zs + k4*(16*64) + er*64;
        zi += z[ec]; zf += z[16 + ec]; zg += z[32 + ec]; zo += z[48 + ec];
      }
      float cc = rc ? 0.f : cst;
      float ig = 1.f/(1.f + __expf(-zi));
      float fg = 1.f/(1.f + __expf(-zf));
      float og = 1.f/(1.f + __expf(-zo));
      cc = fg*cc + ig*tanhx(zg);
      float nh = og*tanhx(cc);
      cst = cc;
      int hcol = ni*16 + ec;

      unsigned yu = (unsigned)__half_as_ushort(__float2half(nh));
      unsigned yhi = __shfl_down_sync(0xffffffffu, yu, 1);
      unsigned hu = rn ? 0u : yu;
      unsigned hhi = __shfl_down_sync(0xffffffffu, hu, 1);
      if ((ec & 1) == 0){
        int pp = hcol >> 1;
        unsigned* hd = (unsigned*)hn + (((mbase+er)*4 + (pp & 3))*64 + (pp >> 2));
        asm volatile("st.global.cg.u32 [%0], %1;" :: "l"(hd), "r"(hu | (hhi << 16)) : "memory");
        unsigned* yd = (unsigned*)g_Ah + ((rg*512 + hcol) >> 1);
        asm volatile("st.global.cg.u32 [%0], %1;" :: "l"(yd), "r"(yu | (yhi << 16)) : "memory");
      }
      if (emb) emb[rg*512 + hcol] = nh;
      if (t == TT-1){
        coutP[(size_t)(mbase+er)*512 + hcol] = cc;
        houtP[(size_t)(mbase+er)*512 + hcol] = nh;
      }
    }
    if (t < TT-1) gbar_flag(mg, ni, (unsigned)(t + 1));
  }
}

// ---------------- logits ----------------
__global__ __launch_bounds__(256) void logits_k(
    const float* __restrict__ W, const float* __restrict__ b, float* __restrict__ C)
{
  __shared__ float Ws[512*20];
  int tid = threadIdx.x;
  for (int i = tid; i < 512*20; i += 256) Ws[i] = W[i];
  __syncthreads();
  int row = blockIdx.x*8 + (tid >> 5), lane = tid & 31;
  float acc[20];
  #pragma unroll
  for (int c = 0; c < 20; c++) acc[c] = 0.f;
  #pragma unroll 4
  for (int j = 0; j < 16; j++){
    float a = g_hpre[(size_t)row*512 + lane + j*32];
    const float* w = &Ws[(lane + j*32)*20];
    #pragma unroll
    for (int c = 0; c < 20; c++) acc[c] += a*w[c];
  }
  #pragma unroll
  for (int c = 0; c < 20; c++)
    #pragma unroll
    for (int o = 16; o; o >>= 1) acc[c] += __shfl_xor_sync(0xffffffffu, acc[c], o);
  if (lane < 20) C[(size_t)row*20 + lane] = acc[lane] + b[lane];
}

// ---------------- launcher ----------------
extern "C" void kernel_launch(void* const* d_in, const int*, int, void* d_out_, int){
  const float* x     = (const float*)d_in[0];
  const void*  rsts  = d_in[1];
  const float* cc    = (const float*)d_in[2];
  const float* ch    = (const float*)d_in[3];
  const float* preW  = (const float*)d_in[4];
  const float* preb  = (const float*)d_in[5];
  const float* lns   = (const float*)d_in[6];
  const float* lnb   = (const float*)d_in[7];
  const float* Wi0   = (const float*)d_in[8];
  const float* Wh0   = (const float*)d_in[9];
  const float* b0    = (const float*)d_in[10];
  const float* Wi1   = (const float*)d_in[11];
  const float* Wh1   = (const float*)d_in[12];
  const float* b1    = (const float*)d_in[13];
  const float* postW = (const float*)d_in[14];
  const float* postb = (const float*)d_in[15];
  const float* outW  = (const float*)d_in[16];
  const float* outb  = (const float*)d_in[17];
  float* out = (float*)d_out_;
  const size_t OC = 0, OH = 131072, OL = 262144, OE = 1572864;

  cudaFuncSetAttribute(gemm_h<false>, cudaFuncAttributeMaxDynamicSharedMemorySize, GEMM_SMEM);
  cudaFuncSetAttribute(gemm_h<true>,  cudaFuncAttributeMaxDynamicSharedMemorySize, GEMM_SMEM);
  cudaFuncSetAttribute(rec_lstm, cudaFuncAttributeMaxDynamicSharedMemorySize, RECSMEM);

  detect_resets<<<1,256>>>((const unsigned char*)rsts);
  conv_resets<<<256,256>>>(rsts);
  dim3 g512(4,512), g2048(16,512);
  dim3 tp512(16,16), tp2048(64,16);

  conv_x<<<32768,256>>>(x, (size_t)TB*HH/4);
  pack_bh<<<tp512,256>>>(preW, 512);
  gemm_h<false><<<g512,256,GEMM_SMEM>>>(preb, 0, 512);
  ln_relu<<<8192,256>>>(lns, lnb);

  pack_bh<<<tp2048,256>>>(Wi0, 2048);
  gemm_h<false><<<g2048,256,GEMM_SMEM>>>(b0, 0, 2048);
  pack_wh<<<2048,512>>>(Wh0, 0);
  init_rec<<<256,256>>>(ch);
  rec_lstm<<<256,256,RECSMEM>>>(0, cc, nullptr, out + OC, out + OH);

  pack_bh<<<tp2048,256>>>(Wi1, 2048);
  gemm_h<false><<<g2048,256,GEMM_SMEM>>>(b1, 0, 2048);
  pack_wh<<<2048,512>>>(Wh1, 1);
  init_rec<<<256,256>>>(ch + 65536);
  rec_lstm<<<256,256,RECSMEM>>>(1, cc + 65536, out + OE,
                                out + OC + 65536, out + OH + 65536);

  pack_bh<<<tp512,256>>>(postW, 512);
  gemm_h<true><<<g512,256,GEMM_SMEM>>>(postb, 1, 512);
  logits_k<<<8192,256>>>(outW, outb, out + OL);
}

// round 16
// speedup vs baseline: 1.6219x; 1.0119x over previous
#include <cuda_runtime.h>
#include <cuda_fp16.h>
#include <math.h>

#define TT 512
#define BB 128
#define HH 512
#define NZ 2048
#define TB 65536

// ---------------- static device scratch ----------------
__device__ float g_zx[(size_t)TB*NZ];
__device__ float g_hpre[(size_t)TB*HH];
__device__ __half g_Ah[(size_t)TB*HH];           // fp16 GEMM A staging (reused)
__device__ __half g_wBh[2048*512];               // fp16 GEMM B, [n][k]
__device__ unsigned g_WhpU[2][(size_t)NZ*HH/2];  // half2: [(nc*4+p%4)*64 + p/4]
__device__ unsigned g_hbufU[2][BB*HH/2];         // half2: [(row*4+p%4)*64 + p/4]
__device__ unsigned char g_rst[TB];
__device__ unsigned g_flag[8][32*32];            // per-CTA barrier flags, 128B stride
__device__ int g_rmode;

__device__ __forceinline__ void mma16(float* c, const unsigned* a, const unsigned* b){
  asm volatile("mma.sync.aligned.m16n8k16.row.col.f32.f16.f16.f32 "
    "{%0,%1,%2,%3},{%4,%5,%6,%7},{%8,%9},{%0,%1,%2,%3};"
    : "+f"(c[0]),"+f"(c[1]),"+f"(c[2]),"+f"(c[3])
    : "r"(a[0]),"r"(a[1]),"r"(a[2]),"r"(a[3]),"r"(b[0]),"r"(b[1]));
}
__device__ __forceinline__ void cpa16(void* dst, const void* src){
  unsigned d = (unsigned)__cvta_generic_to_shared(dst);
  asm volatile("cp.async.cg.shared.global [%0], [%1], 16;" :: "r"(d), "l"(src));
}
__device__ __forceinline__ void ldsm4(unsigned* r, unsigned saddr){
  asm volatile("ldmatrix.sync.aligned.m8n8.x4.shared.b16 {%0,%1,%2,%3}, [%4];"
    : "=r"(r[0]),"=r"(r[1]),"=r"(r[2]),"=r"(r[3]) : "r"(saddr));
}
__device__ __forceinline__ void ldsm2(unsigned* r, unsigned saddr){
  asm volatile("ldmatrix.sync.aligned.m8n8.x2.shared.b16 {%0,%1}, [%2];"
    : "=r"(r[0]),"=r"(r[1]) : "r"(saddr));
}
__device__ __forceinline__ float tanhx(float x){
  return 1.f - __fdividef(2.f, __expf(2.f*x) + 1.f);
}

// ---------------- resets dtype detect + convert ----------------
__global__ void detect_resets(const unsigned char* p){
  __shared__ int cF, c1;
  if (threadIdx.x == 0){ cF = 0; c1 = 0; }
  __syncthreads();
  for (int i = threadIdx.x; i < 65536; i += 256){
    unsigned char v = p[i];
    if (v == 0x3f || v == 0x80) atomicAdd(&cF, 1);
    else if (v == 1 && (i & 3)) atomicAdd(&c1, 1);
  }
  __syncthreads();
  if (threadIdx.x == 0) g_rmode = cF ? 2 : (c1 ? 1 : 0);
}
__global__ void conv_resets(const void* p){
  int i = blockIdx.x*blockDim.x + threadIdx.x;
  int m = g_rmode;
  bool z;
  if (m == 1)      z = ((const unsigned char*)p)[i] != 0;
  else if (m == 2) z = ((const float*)p)[i] != 0.f;
  else             z = ((const int*)p)[i] != 0;
  g_rst[i] = z ? 1 : 0;
}

// ---------------- fp32 -> fp16 A staging ----------------
__global__ void conv_x(const float* __restrict__ X, size_t n4){
  size_t i = (size_t)blockIdx.x*blockDim.x + threadIdx.x;
  if (i < n4){
    float4 v = *(const float4*)&X[i*4];
    unsigned lo = __half_as_ushort(__float2half(v.x)) |
                  ((unsigned)__half_as_ushort(__float2half(v.y)) << 16);
    unsigned hi = __half_as_ushort(__float2half(v.z)) |
                  ((unsigned)__half_as_ushort(__float2half(v.w)) << 16);
    ((uint2*)g_Ah)[i] = make_uint2(lo, hi);
  }
}

// ---------------- B transpose+convert: [k][N] f32 -> [n][512] f16 ----------
__global__ void pack_bh(const float* __restrict__ B, int N){
  __shared__ float t[32][33];
  int bx = blockIdx.x*32, by = blockIdx.y*32;
  int lx = threadIdx.x & 31, ly = threadIdx.x >> 5;
  #pragma unroll
  for (int q = 0; q < 32; q += 8)
    t[ly+q][lx] = B[(size_t)(by+ly+q)*N + bx+lx];
  __syncthreads();
  #pragma unroll
  for (int q = 0; q < 32; q += 8)
    g_wBh[(size_t)(bx+ly+q)*512 + by+lx] = __float2half(t[lx][ly+q]);
}

// pack Wh[512][2048] -> fp16 pair-packed layout
__global__ void pack_wh(const float* __restrict__ Wh, int L){
  __half* dst = (__half*)g_WhpU[L];
  for (size_t idx = blockIdx.x*blockDim.x + threadIdx.x; idx < (size_t)HH*NZ;
       idx += (size_t)gridDim.x*blockDim.x){
    int k = idx >> 11, j = idx & (NZ-1);
    int g = j >> 9, r = j & 511;
    int nc = ((r >> 4) << 6) + (g << 4) + (r & 15);
    int p = k >> 1;
    dst[(((size_t)nc*4 + (p & 3))*64 + (p >> 2))*2 + (k & 1)] = __float2half(Wh[idx]);
  }
}

// init h buffer (fp16) with reset for t=0 pre-applied + flags
__global__ void init_rec(const float* __restrict__ carryH){
  int i = blockIdx.x*blockDim.x + threadIdx.x;
  if (i < BB*HH){
    int row = i >> 9, col = i & 511;
    float v = g_rst[row] ? 0.f : carryH[i];
    int p = col >> 1;
    ((__half*)g_hbufU[0])[((row*4 + (p & 3))*64 + (p >> 2))*2 + (col & 1)] = __float2half(v);
  }
  if (i < 8*32*32) ((unsigned*)g_flag)[i] = 0u;
}

// ---------------- bulk fp16 GEMM (4-stage cp.async + ldmatrix) -------------
#define GS 20
#define NSTG 4
#define GEMM_SMEM (2*NSTG*128*GS*4)
#define HA(st,r,p) shA[((st)*128+(r))*GS + (p)]
#define HB(st,n,p) shB[((st)*128+(n))*GS + (p)]

template<bool RELU>
__global__ __launch_bounds__(256,2) void gemm_h(
    const float* __restrict__ bias, int cSel, int N)
{
  extern __shared__ unsigned shu[];
  unsigned* shA = shu;
  unsigned* shB = shu + NSTG*128*GS;
  float* C = (cSel == 1) ? g_hpre : g_zx;
  const int mt = blockIdx.y, nt = blockIdx.x, tid = threadIdx.x;
  const int wid = tid >> 5, lane = tid & 31, gID = lane >> 2, tig = lane & 3;
  const int wM = wid >> 1, wN = wid & 1;

  float acc[2][8][4];
  #pragma unroll
  for (int mi = 0; mi < 2; mi++)
    #pragma unroll
    for (int ni = 0; ni < 8; ni++)
      #pragma unroll
      for (int q = 0; q < 4; q++) acc[mi][ni][q] = 0.f;

  // ldmatrix base addresses (st=0, kk=0); per-iteration offsets are immediates
  const unsigned aBase = (unsigned)__cvta_generic_to_shared(
      &HA(0, wM*32 + (lane & 15), (lane >> 4) << 2));
  const unsigned bBase = (unsigned)__cvta_generic_to_shared(
      &HB(0, wN*64 + (lane & 7), ((lane >> 3) & 1) << 2));

  auto issue = [&](int kt, int st){
    #pragma unroll
    for (int i = 0; i < 2; i++){
      int c = tid + i*256, r = c >> 2, po = c & 3;
      cpa16(&HA(st, r, po*4), &g_Ah[(size_t)(mt*128 + r)*512 + kt*32 + po*8]);
    }
    #pragma unroll
    for (int i = 0; i < 2; i++){
      int c = tid + i*256, n = c >> 2, po = c & 3;
      cpa16(&HB(st, n, po*4), &g_wBh[(size_t)(nt*128 + n)*512 + kt*32 + po*8]);
    }
    asm volatile("cp.async.commit_group;" ::: "memory");
  };

  issue(0, 0); issue(1, 1); issue(2, 2); issue(3, 3);
  int st = 0;
  for (int kt = 0; kt < 16; kt++){
    if (kt <= 12)      asm volatile("cp.async.wait_group 3;" ::: "memory");
    else if (kt == 13) asm volatile("cp.async.wait_group 2;" ::: "memory");
    else if (kt == 14) asm volatile("cp.async.wait_group 1;" ::: "memory");
    else               asm volatile("cp.async.wait_group 0;" ::: "memory");
    __syncthreads();
    unsigned stoff = (unsigned)(st*128*GS*4);
    #pragma unroll
    for (int kk = 0; kk < 2; kk++){
      unsigned koff = stoff + kk*32;
      unsigned a[2][4], b[8][2];
      #pragma unroll
      for (int mi = 0; mi < 2; mi++)
        ldsm4(a[mi], aBase + koff + mi*(16*GS*4));
      #pragma unroll
      for (int ni = 0; ni < 8; ni++)
        ldsm2(b[ni], bBase + koff + ni*(8*GS*4));
      #pragma unroll
      for (int mi = 0; mi < 2; mi++)
        #pragma unroll
        for (int ni = 0; ni < 8; ni++)
          mma16(acc[mi][ni], a[mi], b[ni]);
    }
    __syncthreads();
    if (kt + NSTG < 16) issue(kt + NSTG, st);
    st = (st == NSTG-1) ? 0 : st + 1;
  }

  #pragma unroll
  for (int mi = 0; mi < 2; mi++){
    int r0 = mt*128 + wM*32 + mi*16 + gID;
    #pragma unroll
    for (int ni = 0; ni < 8; ni++){
      int col = nt*128 + wN*64 + ni*8 + tig*2;
      float b0 = bias[col], b1 = bias[col+1];
      float v0 = acc[mi][ni][0]+b0, v1 = acc[mi][ni][1]+b1;
      float v2 = acc[mi][ni][2]+b0, v3 = acc[mi][ni][3]+b1;
      if (RELU){ v0=fmaxf(v0,0.f); v1=fmaxf(v1,0.f); v2=fmaxf(v2,0.f); v3=fmaxf(v3,0.f); }
      *(float2*)&C[(size_t)r0*N + col]     = make_float2(v0, v1);
      *(float2*)&C[(size_t)(r0+8)*N + col] = make_float2(v2, v3);
    }
  }
}

// ---------------- LayerNorm + ReLU (fp32 g_zx -> fp16 g_Ah) ----------------
__global__ __launch_bounds__(256) void ln_relu(
    const float* __restrict__ sc, const float* __restrict__ bi)
{
  int row = blockIdx.x*8 + (threadIdx.x >> 5), lane = threadIdx.x & 31;
  float v[16], s = 0.f, s2 = 0.f;
  const float* src = &g_zx[(size_t)row*512 + lane*16];
  #pragma unroll
  for (int q = 0; q < 4; q++){
    float4 f = *(const float4*)&src[q*4];
    v[q*4]=f.x; v[q*4+1]=f.y; v[q*4+2]=f.z; v[q*4+3]=f.w;
    s += f.x+f.y+f.z+f.w;
    s2 += f.x*f.x+f.y*f.y+f.z*f.z+f.w*f.w;
  }
  #pragma unroll
  for (int o = 16; o; o >>= 1){
    s  += __shfl_xor_sync(0xffffffffu, s,  o);
    s2 += __shfl_xor_sync(0xffffffffu, s2, o);
  }
  float mu = s*(1.f/512.f);
  float var = fmaxf(s2*(1.f/512.f) - mu*mu, 0.f);
  float rs = rsqrtf(var + 1e-6f);
  unsigned* dst = (unsigned*)&g_Ah[(size_t)row*512 + lane*16];
  #pragma unroll
  for (int q = 0; q < 8; q++){
    int col = lane*16 + q*2;
    float y0 = fmaxf((v[q*2]  -mu)*rs*sc[col]   + bi[col],   0.f);
    float y1 = fmaxf((v[q*2+1]-mu)*rs*sc[col+1] + bi[col+1], 0.f);
    dst[q] = __half_as_ushort(__float2half(y0)) |
             ((unsigned)__half_as_ushort(__float2half(y1)) << 16);
  }
}

// ---------------- persistent LSTM layer: 256 CTAs, 2/SM -------------------
// smem: Bs 256x64 u32 (64KB) | As 64x64 u32 (16KB) | Zs 4x16x64 f32 (16KB)
#define RECSMEM ((256*64 + 64*64)*4 + 4*16*64*4)

// distributed flag barrier: arrive = 1 uncontended release store; wait =
// 32 threads poll the 32 group flags in parallel (monotonic value t+1).
__device__ __forceinline__ void gbar_flag(int mg, int cig, unsigned tgt){
  __syncthreads();
  if (threadIdx.x == 0){
    asm volatile("st.release.gpu.global.u32 [%0], %1;"
                 :: "l"(&g_flag[mg][cig*32]), "r"(tgt) : "memory");
  }
  if (threadIdx.x < 32){
    unsigned g;
    do {
      asm volatile("ld.acquire.gpu.global.u32 %0, [%1];"
                   : "=r"(g) : "l"(&g_flag[mg][threadIdx.x*32]) : "memory");
    } while (g < tgt);
  }
  __syncthreads();
}

__global__ __launch_bounds__(256,2) void rec_lstm(
    int L, const float* __restrict__ carryC,
    float* __restrict__ emb, float* __restrict__ coutP, float* __restrict__ houtP)
{
  extern __shared__ unsigned smu[];
  unsigned* Bs2 = smu;                 // [256][64] half2, swizzled
  unsigned* As2 = smu + 256*64;        // [64][64] half2, swizzled (16 rows)
  float* Zs = (float*)(smu + 320*64);  // [4][16][64]

  const unsigned* WhpU = g_WhpU[L];
  const int tid = threadIdx.x, cta = blockIdx.x;
  const int mg = cta >> 5, mbase = mg*16, ni = cta & 31;
  const int wid = tid >> 5, lane = tid & 31, gID = lane >> 2, tig = lane & 3;
  const int wN = wid & 1, wK = wid >> 1;

  // resident Wh slice: 256 sub-rows x 64 uints
  for (int idx = tid; idx < 256*16; idx += 256){
    int r = idx >> 4, j4 = (idx & 15)*4;
    *(uint4*)&Bs2[r*64 + (j4 ^ ((r & 7) << 2))] =
      *(const uint4*)&WhpU[((size_t)ni*256 + r)*64 + j4];
  }
  // one gate element per thread
  const int er = tid >> 4, ec = tid & 15;
  float cst = carryC[(size_t)(mbase+er)*512 + ni*16 + ec];

  int baseA[2], sA[2], baseB[4], sB[4];
  #pragma unroll
  for (int q = 0; q < 2; q++){
    int ra = (q*8 + gID)*4 + tig;
    baseA[q] = ra*64; sA[q] = (ra & 7) << 2;
  }
  #pragma unroll
  for (int q = 0; q < 4; q++){
    int rb = (wN*32 + q*8 + gID)*4 + tig;
    baseB[q] = rb*64; sB[q] = (rb & 7) << 2;
  }

  for (int t = 0; t < TT; t++){
    const unsigned* hb = g_hbufU[t & 1];
    __half* hn = (__half*)g_hbufU[(t & 1) ^ 1];

    // As fill: 16 rows = 64 sub-rows x 16 uint4
    #pragma unroll
    for (int i = 0; i < 4; i++){
      int idx = tid + i*256;
      int r = idx >> 4, j4 = (idx & 15)*4;
      cpa16(&As2[r*64 + (j4 ^ ((r & 7) << 2))], &hb[(mbase*4 + r)*64 + j4]);
    }
    asm volatile("cp.async.commit_group;" ::: "memory");

    // prefetch Zx + resets (overlaps cp.async)
    float pz[4]; int rc, rn;
    {
      const float* zxr = &g_zx[((size_t)t*128 + mbase + er)*NZ + ni*16 + ec];
      pz[0] = __ldg(zxr);
      pz[1] = __ldg(zxr + 512);
      pz[2] = __ldg(zxr + 1024);
      pz[3] = __ldg(zxr + 1536);
      rc = g_rst[t*128 + mbase + er];
      rn = (t == TT-1) ? 0 : g_rst[(t+1)*128 + mbase + er];
    }
    asm volatile("cp.async.wait_group 0;" ::: "memory");
    __syncthreads();

    {
      float acc[4][4];
      #pragma unroll
      for (int nb = 0; nb < 4; nb++)
        #pragma unroll
        for (int q = 0; q < 4; q++) acc[nb][q] = 0.f;

      #pragma unroll
      for (int jj = 0; jj < 16; jj += 4){
        int j = wK*16 + jj;
        uint4 av[2], bv[4];
        #pragma unroll
        for (int q = 0; q < 2; q++)
          av[q] = *(const uint4*)&As2[baseA[q] + (j ^ sA[q])];
        #pragma unroll
        for (int q = 0; q < 4; q++)
          bv[q] = *(const uint4*)&Bs2[baseB[q] + (j ^ sB[q])];
        unsigned Alo[4] = {av[0].x, av[1].x, av[0].y, av[1].y};
        unsigned Ahi[4] = {av[0].z, av[1].z, av[0].w, av[1].w};
        #pragma unroll
        for (int nb = 0; nb < 4; nb++){
          unsigned Blo[2] = {bv[nb].x, bv[nb].y};
          mma16(acc[nb], Alo, Blo);
          unsigned Bhi[2] = {bv[nb].z, bv[nb].w};
          mma16(acc[nb], Ahi, Bhi);
        }
      }
      float* z = Zs + wK*(16*64);
      int zr = gID;
      #pragma unroll
      for (int nb = 0; nb < 4; nb++){
        int zc = wN*32 + nb*8 + tig*2;
        z[zr*64 + zc]         = acc[nb][0];
        z[zr*64 + zc + 1]     = acc[nb][1];
        z[(zr+8)*64 + zc]     = acc[nb][2];
        z[(zr+8)*64 + zc + 1] = acc[nb][3];
      }
    }
    __syncthreads();

    {
      size_t rg = (size_t)t*128 + mbase + er;
      float zi = pz[0], zf = pz[1], zg = pz[2], zo = pz[3];
      #pragma unroll
      for (int k4 = 0; k4 < 4; k4++){
        const float* z = Zs + k4*(16*64) + er*64;
        zi += z[ec]; zf += z[16 + ec]; zg += z[32 + ec]; zo += z[48 + ec];
      }
      float cc = rc ? 0.f : cst;
      float ig = 1.f/(1.f + __expf(-zi));
      float fg = 1.f/(1.f + __expf(-zf));
      float og = 1.f/(1.f + __expf(-zo));
      cc = fg*cc + ig*tanhx(zg);
      float nh = og*tanhx(cc);
      cst = cc;
      int hcol = ni*16 + ec;

      unsigned yu = (unsigned)__half_as_ushort(__float2half(nh));
      unsigned yhi = __shfl_down_sync(0xffffffffu, yu, 1);
      unsigned hu = rn ? 0u : yu;
      unsigned hhi = __shfl_down_sync(0xffffffffu, hu, 1);
      if ((ec & 1) == 0){
        int pp = hcol >> 1;
        unsigned* hd = (unsigned*)hn + (((mbase+er)*4 + (pp & 3))*64 + (pp >> 2));
        asm volatile("st.global.cg.u32 [%0], %1;" :: "l"(hd), "r"(hu | (hhi << 16)) : "memory");
        unsigned* yd = (unsigned*)g_Ah + ((rg*512 + hcol) >> 1);
        asm volatile("st.global.cg.u32 [%0], %1;" :: "l"(yd), "r"(yu | (yhi << 16)) : "memory");
      }
      if (emb) emb[rg*512 + hcol] = nh;
      if (t == TT-1){
        coutP[(size_t)(mbase+er)*512 + hcol] = cc;
        houtP[(size_t)(mbase+er)*512 + hcol] = nh;
      }
    }
    if (t < TT-1) gbar_flag(mg, ni, (unsigned)(t + 1));
  }
}

// ---------------- logits ----------------
__global__ __launch_bounds__(256) void logits_k(
    const float* __restrict__ W, const float* __restrict__ b, float* __restrict__ C)
{
  __shared__ float Ws[512*20];
  int tid = threadIdx.x;
  for (int i = tid; i < 512*20; i += 256) Ws[i] = W[i];
  __syncthreads();
  int row = blockIdx.x*8 + (tid >> 5), lane = tid & 31;
  float acc[20];
  #pragma unroll
  for (int c = 0; c < 20; c++) acc[c] = 0.f;
  #pragma unroll 4
  for (int j = 0; j < 16; j++){
    float a = g_hpre[(size_t)row*512 + lane + j*32];
    const float* w = &Ws[(lane + j*32)*20];
    #pragma unroll
    for (int c = 0; c < 20; c++) acc[c] += a*w[c];
  }
  #pragma unroll
  for (int c = 0; c < 20; c++)
    #pragma unroll
    for (int o = 16; o; o >>= 1) acc[c] += __shfl_xor_sync(0xffffffffu, acc[c], o);
  if (lane < 20) C[(size_t)row*20 + lane] = acc[lane] + b[lane];
}

// ---------------- launcher ----------------
extern "C" void kernel_launch(void* const* d_in, const int*, int, void* d_out_, int){
  const float* x     = (const float*)d_in[0];
  const void*  rsts  = d_in[1];
  const float* cc    = (const float*)d_in[2];
  const float* ch    = (const float*)d_in[3];
  const float* preW  = (const float*)d_in[4];
  const float* preb  = (const float*)d_in[5];
  const float* lns   = (const float*)d_in[6];
  const float* lnb   = (const float*)d_in[7];
  const float* Wi0   = (const float*)d_in[8];
  const float* Wh0   = (const float*)d_in[9];
  const float* b0    = (const float*)d_in[10];
  const float* Wi1   = (const float*)d_in[11];
  const float* Wh1   = (const float*)d_in[12];
  const float* b1    = (const float*)d_in[13];
  const float* postW = (const float*)d_in[14];
  const float* postb = (const float*)d_in[15];
  const float* outW  = (const float*)d_in[16];
  const float* outb  = (const float*)d_in[17];
  float* out = (float*)d_out_;
  const size_t OC = 0, OH = 131072, OL = 262144, OE = 1572864;

  cudaFuncSetAttribute(gemm_h<false>, cudaFuncAttributeMaxDynamicSharedMemorySize, GEMM_SMEM);
  cudaFuncSetAttribute(gemm_h<true>,  cudaFuncAttributeMaxDynamicSharedMemorySize, GEMM_SMEM);
  cudaFuncSetAttribute(rec_lstm, cudaFuncAttributeMaxDynamicSharedMemorySize, RECSMEM);

  detect_resets<<<1,256>>>((const unsigned char*)rsts);
  conv_resets<<<256,256>>>(rsts);
  dim3 g512(4,512), g2048(16,512);
  dim3 tp512(16,16), tp2048(64,16);

  conv_x<<<32768,256>>>(x, (size_t)TB*HH/4);
  pack_bh<<<tp512,256>>>(preW, 512);
  gemm_h<false><<<g512,256,GEMM_SMEM>>>(preb, 0, 512);
  ln_relu<<<8192,256>>>(lns, lnb);

  pack_bh<<<tp2048,256>>>(Wi0, 2048);
  gemm_h<false><<<g2048,256,GEMM_SMEM>>>(b0, 0, 2048);
  pack_wh<<<2048,512>>>(Wh0, 0);
  init_rec<<<256,256>>>(ch);
  rec_lstm<<<256,256,RECSMEM>>>(0, cc, nullptr, out + OC, out + OH);

  pack_bh<<<tp2048,256>>>(Wi1, 2048);
  gemm_h<false><<<g2048,256,GEMM_SMEM>>>(b1, 0, 2048);
  pack_wh<<<2048,512>>>(Wh1, 1);
  init_rec<<<256,256>>>(ch + 65536);
  rec_lstm<<<256,256,RECSMEM>>>(1, cc + 65536, out + OE,
                                out + OC + 65536, out + OH + 65536);

  pack_bh<<<tp512,256>>>(postW, 512);
  gemm_h<true><<<g512,256,GEMM_SMEM>>>(postb, 1, 512);
  logits_k<<<8192,256>>>(outW, outb, out + OL);
}

// round 17
// speedup vs baseline: 1.6257x; 1.0023x over previous
#include <cuda_runtime.h>
#include <cuda_fp16.h>
#include <math.h>

#define TT 512
#define BB 128
#define HH 512
#define NZ 2048
#define TB 65536

// ---------------- static device scratch ----------------
__device__ float g_zx[(size_t)TB*NZ];            // pre: fp32 [row][512]; Zx: fp16 [row][2048]
__device__ float g_hpre[(size_t)TB*HH];
__device__ __half g_Ah[(size_t)TB*HH];           // fp16 GEMM A staging (reused)
__device__ __half g_wBh[2048*512];               // fp16 GEMM B, [n][k]
__device__ unsigned g_WhpU[2][(size_t)NZ*HH/2];  // half2: [(nc*4+p%4)*64 + p/4]
__device__ unsigned g_hbufU[2][BB*HH/2];         // half2: [(row*4+p%4)*64 + p/4]
__device__ unsigned char g_rst[TB];
__device__ unsigned g_flag[8][32*32];            // per-CTA barrier flags, 128B stride
__device__ int g_rmode;

__device__ __forceinline__ void mma16(float* c, const unsigned* a, const unsigned* b){
  asm volatile("mma.sync.aligned.m16n8k16.row.col.f32.f16.f16.f32 "
    "{%0,%1,%2,%3},{%4,%5,%6,%7},{%8,%9},{%0,%1,%2,%3};"
    : "+f"(c[0]),"+f"(c[1]),"+f"(c[2]),"+f"(c[3])
    : "r"(a[0]),"r"(a[1]),"r"(a[2]),"r"(a[3]),"r"(b[0]),"r"(b[1]));
}
__device__ __forceinline__ void cpa16(void* dst, const void* src){
  unsigned d = (unsigned)__cvta_generic_to_shared(dst);
  asm volatile("cp.async.cg.shared.global [%0], [%1], 16;" :: "r"(d), "l"(src));
}
__device__ __forceinline__ void ldsm4(unsigned* r, unsigned saddr){
  asm volatile("ldmatrix.sync.aligned.m8n8.x4.shared.b16 {%0,%1,%2,%3}, [%4];"
    : "=r"(r[0]),"=r"(r[1]),"=r"(r[2]),"=r"(r[3]) : "r"(saddr));
}
__device__ __forceinline__ void ldsm2(unsigned* r, unsigned saddr){
  asm volatile("ldmatrix.sync.aligned.m8n8.x2.shared.b16 {%0,%1}, [%2];"
    : "=r"(r[0]),"=r"(r[1]) : "r"(saddr));
}
__device__ __forceinline__ float tanhx(float x){
  return 1.f - __fdividef(2.f, __expf(2.f*x) + 1.f);
}

// ---------------- resets dtype detect + convert ----------------
__global__ void detect_resets(const unsigned char* p){
  __shared__ int cF, c1;
  if (threadIdx.x == 0){ cF = 0; c1 = 0; }
  __syncthreads();
  for (int i = threadIdx.x; i < 65536; i += 256){
    unsigned char v = p[i];
    if (v == 0x3f || v == 0x80) atomicAdd(&cF, 1);
    else if (v == 1 && (i & 3)) atomicAdd(&c1, 1);
  }
  __syncthreads();
  if (threadIdx.x == 0) g_rmode = cF ? 2 : (c1 ? 1 : 0);
}
__global__ void conv_resets(const void* p){
  int i = blockIdx.x*blockDim.x + threadIdx.x;
  int m = g_rmode;
  bool z;
  if (m == 1)      z = ((const unsigned char*)p)[i] != 0;
  else if (m == 2) z = ((const float*)p)[i] != 0.f;
  else             z = ((const int*)p)[i] != 0;
  g_rst[i] = z ? 1 : 0;
}

// ---------------- fp32 -> fp16 A staging ----------------
__global__ void conv_x(const float* __restrict__ X, size_t n4){
  size_t i = (size_t)blockIdx.x*blockDim.x + threadIdx.x;
  if (i < n4){
    float4 v = *(const float4*)&X[i*4];
    unsigned lo = __half_as_ushort(__float2half(v.x)) |
                  ((unsigned)__half_as_ushort(__float2half(v.y)) << 16);
    unsigned hi = __half_as_ushort(__float2half(v.z)) |
                  ((unsigned)__half_as_ushort(__float2half(v.w)) << 16);
    ((uint2*)g_Ah)[i] = make_uint2(lo, hi);
  }
}

// ---------------- B transpose+convert: [k][N] f32 -> [n][512] f16 ----------
__global__ void pack_bh(const float* __restrict__ B, int N){
  __shared__ float t[32][33];
  int bx = blockIdx.x*32, by = blockIdx.y*32;
  int lx = threadIdx.x & 31, ly = threadIdx.x >> 5;
  #pragma unroll
  for (int q = 0; q < 32; q += 8)
    t[ly+q][lx] = B[(size_t)(by+ly+q)*N + bx+lx];
  __syncthreads();
  #pragma unroll
  for (int q = 0; q < 32; q += 8)
    g_wBh[(size_t)(bx+ly+q)*512 + by+lx] = __float2half(t[lx][ly+q]);
}

// pack Wh[512][2048] -> fp16 pair-packed layout
__global__ void pack_wh(const float* __restrict__ Wh, int L){
  __half* dst = (__half*)g_WhpU[L];
  for (size_t idx = blockIdx.x*blockDim.x + threadIdx.x; idx < (size_t)HH*NZ;
       idx += (size_t)gridDim.x*blockDim.x){
    int k = idx >> 11, j = idx & (NZ-1);
    int g = j >> 9, r = j & 511;
    int nc = ((r >> 4) << 6) + (g << 4) + (r & 15);
    int p = k >> 1;
    dst[(((size_t)nc*4 + (p & 3))*64 + (p >> 2))*2 + (k & 1)] = __float2half(Wh[idx]);
  }
}

// init h buffer (fp16) with reset for t=0 pre-applied + flags
__global__ void init_rec(const float* __restrict__ carryH){
  int i = blockIdx.x*blockDim.x + threadIdx.x;
  if (i < BB*HH){
    int row = i >> 9, col = i & 511;
    float v = g_rst[row] ? 0.f : carryH[i];
    int p = col >> 1;
    ((__half*)g_hbufU[0])[((row*4 + (p & 3))*64 + (p >> 2))*2 + (col & 1)] = __float2half(v);
  }
  if (i < 8*32*32) ((unsigned*)g_flag)[i] = 0u;
}

// ---------------- bulk fp16 GEMM (4-stage cp.async + ldmatrix) -------------
#define GS 20
#define NSTG 4
#define GEMM_SMEM (2*NSTG*128*GS*4)
#define HA(st,r,p) shA[((st)*128+(r))*GS + (p)]
#define HB(st,n,p) shB[((st)*128+(n))*GS + (p)]

template<bool RELU, bool HOUT>
__global__ __launch_bounds__(256,2) void gemm_h(
    const float* __restrict__ bias, int cSel, int N)
{
  extern __shared__ unsigned shu[];
  unsigned* shA = shu;
  unsigned* shB = shu + NSTG*128*GS;
  float* C = (cSel == 1) ? g_hpre : g_zx;
  __half* Ch = (__half*)g_zx;
  const int mt = blockIdx.y, nt = blockIdx.x, tid = threadIdx.x;
  const int wid = tid >> 5, lane = tid & 31, gID = lane >> 2, tig = lane & 3;
  const int wM = wid >> 1, wN = wid & 1;

  float acc[2][8][4];
  #pragma unroll
  for (int mi = 0; mi < 2; mi++)
    #pragma unroll
    for (int ni = 0; ni < 8; ni++)
      #pragma unroll
      for (int q = 0; q < 4; q++) acc[mi][ni][q] = 0.f;

  // ldmatrix base addresses (st=0, kk=0); per-iteration offsets are immediates
  const unsigned aBase = (unsigned)__cvta_generic_to_shared(
      &HA(0, wM*32 + (lane & 15), (lane >> 4) << 2));
  const unsigned bBase = (unsigned)__cvta_generic_to_shared(
      &HB(0, wN*64 + (lane & 7), ((lane >> 3) & 1) << 2));

  auto issue = [&](int kt, int st){
    #pragma unroll
    for (int i = 0; i < 2; i++){
      int c = tid + i*256, r = c >> 2, po = c & 3;
      cpa16(&HA(st, r, po*4), &g_Ah[(size_t)(mt*128 + r)*512 + kt*32 + po*8]);
    }
    #pragma unroll
    for (int i = 0; i < 2; i++){
      int c = tid + i*256, n = c >> 2, po = c & 3;
      cpa16(&HB(st, n, po*4), &g_wBh[(size_t)(nt*128 + n)*512 + kt*32 + po*8]);
    }
    asm volatile("cp.async.commit_group;" ::: "memory");
  };

  issue(0, 0); issue(1, 1); issue(2, 2); issue(3, 3);
  int st = 0;
  for (int kt = 0; kt < 16; kt++){
    if (kt <= 12)      asm volatile("cp.async.wait_group 3;" ::: "memory");
    else if (kt == 13) asm volatile("cp.async.wait_group 2;" ::: "memory");
    else if (kt == 14) asm volatile("cp.async.wait_group 1;" ::: "memory");
    else               asm volatile("cp.async.wait_group 0;" ::: "memory");
    __syncthreads();
    unsigned stoff = (unsigned)(st*128*GS*4);
    #pragma unroll
    for (int kk = 0; kk < 2; kk++){
      unsigned koff = stoff + kk*32;
      unsigned a[2][4], b[8][2];
      #pragma unroll
      for (int mi = 0; mi < 2; mi++)
        ldsm4(a[mi], aBase + koff + mi*(16*GS*4));
      #pragma unroll
      for (int ni = 0; ni < 8; ni++)
        ldsm2(b[ni], bBase + koff + ni*(8*GS*4));
      #pragma unroll
      for (int mi = 0; mi < 2; mi++)
        #pragma unroll
        for (int ni = 0; ni < 8; ni++)
          mma16(acc[mi][ni], a[mi], b[ni]);
    }
    __syncthreads();
    if (kt + NSTG < 16) issue(kt + NSTG, st);
    st = (st == NSTG-1) ? 0 : st + 1;
  }

  #pragma unroll
  for (int mi = 0; mi < 2; mi++){
    int r0 = mt*128 + wM*32 + mi*16 + gID;
    #pragma unroll
    for (int ni = 0; ni < 8; ni++){
      int col = nt*128 + wN*64 + ni*8 + tig*2;
      float b0 = bias[col], b1 = bias[col+1];
      float v0 = acc[mi][ni][0]+b0, v1 = acc[mi][ni][1]+b1;
      float v2 = acc[mi][ni][2]+b0, v3 = acc[mi][ni][3]+b1;
      if (RELU){ v0=fmaxf(v0,0.f); v1=fmaxf(v1,0.f); v2=fmaxf(v2,0.f); v3=fmaxf(v3,0.f); }
      if (HOUT){
        unsigned u01 = __half_as_ushort(__float2half(v0)) |
                       ((unsigned)__half_as_ushort(__float2half(v1)) << 16);
        unsigned u23 = __half_as_ushort(__float2half(v2)) |
                       ((unsigned)__half_as_ushort(__float2half(v3)) << 16);
        *(unsigned*)&Ch[(size_t)r0*N + col]     = u01;
        *(unsigned*)&Ch[(size_t)(r0+8)*N + col] = u23;
      } else {
        *(float2*)&C[(size_t)r0*N + col]     = make_float2(v0, v1);
        *(float2*)&C[(size_t)(r0+8)*N + col] = make_float2(v2, v3);
      }
    }
  }
}

// ---------------- LayerNorm + ReLU (fp32 g_zx -> fp16 g_Ah) ----------------
__global__ __launch_bounds__(256) void ln_relu(
    const float* __restrict__ sc, const float* __restrict__ bi)
{
  int row = blockIdx.x*8 + (threadIdx.x >> 5), lane = threadIdx.x & 31;
  float v[16], s = 0.f, s2 = 0.f;
  const float* src = &g_zx[(size_t)row*512 + lane*16];
  #pragma unroll
  for (int q = 0; q < 4; q++){
    float4 f = *(const float4*)&src[q*4];
    v[q*4]=f.x; v[q*4+1]=f.y; v[q*4+2]=f.z; v[q*4+3]=f.w;
    s += f.x+f.y+f.z+f.w;
    s2 += f.x*f.x+f.y*f.y+f.z*f.z+f.w*f.w;
  }
  #pragma unroll
  for (int o = 16; o; o >>= 1){
    s  += __shfl_xor_sync(0xffffffffu, s,  o);
    s2 += __shfl_xor_sync(0xffffffffu, s2, o);
  }
  float mu = s*(1.f/512.f);
  float var = fmaxf(s2*(1.f/512.f) - mu*mu, 0.f);
  float rs = rsqrtf(var + 1e-6f);
  unsigned* dst = (unsigned*)&g_Ah[(size_t)row*512 + lane*16];
  #pragma unroll
  for (int q = 0; q < 8; q++){
    int col = lane*16 + q*2;
    float y0 = fmaxf((v[q*2]  -mu)*rs*sc[col]   + bi[col],   0.f);
    float y1 = fmaxf((v[q*2+1]-mu)*rs*sc[col+1] + bi[col+1], 0.f);
    dst[q] = __half_as_ushort(__float2half(y0)) |
             ((unsigned)__half_as_ushort(__float2half(y1)) << 16);
  }
}

// ---------------- persistent LSTM layer: 256 CTAs, 2/SM -------------------
// smem: Bs 256x64 u32 (64KB) | As 64x64 u32 (16KB) | Zs 4x16x64 f32 (16KB)
#define RECSMEM ((256*64 + 64*64)*4 + 4*16*64*4)

// distributed flag barrier: arrive = 1 uncontended release store; wait =
// 32 threads poll the 32 group flags in parallel (monotonic value t+1).
__device__ __forceinline__ void gbar_flag(int mg, int cig, unsigned tgt){
  __syncthreads();
  if (threadIdx.x == 0){
    asm volatile("st.release.gpu.global.u32 [%0], %1;"
                 :: "l"(&g_flag[mg][cig*32]), "r"(tgt) : "memory");
  }
  if (threadIdx.x < 32){
    unsigned g;
    do {
      asm volatile("ld.acquire.gpu.global.u32 %0, [%1];"
                   : "=r"(g) : "l"(&g_flag[mg][threadIdx.x*32]) : "memory");
    } while (g < tgt);
  }
  __syncthreads();
}

__global__ __launch_bounds__(256,2) void rec_lstm(
    int L, const float* __restrict__ carryC,
    float* __restrict__ emb, float* __restrict__ coutP, float* __restrict__ houtP)
{
  extern __shared__ unsigned smu[];
  unsigned* Bs2 = smu;                 // [256][64] half2, swizzled
  unsigned* As2 = smu + 256*64;        // [64][64] half2, swizzled (16 rows)
  float* Zs = (float*)(smu + 320*64);  // [4][16][64]

  const unsigned* WhpU = g_WhpU[L];
  const int tid = threadIdx.x, cta = blockIdx.x;
  const int mg = cta >> 5, mbase = mg*16, ni = cta & 31;
  const int wid = tid >> 5, lane = tid & 31, gID = lane >> 2, tig = lane & 3;
  const int wN = wid & 1, wK = wid >> 1;

  // resident Wh slice: 256 sub-rows x 64 uints
  for (int idx = tid; idx < 256*16; idx += 256){
    int r = idx >> 4, j4 = (idx & 15)*4;
    *(uint4*)&Bs2[r*64 + (j4 ^ ((r & 7) << 2))] =
      *(const uint4*)&WhpU[((size_t)ni*256 + r)*64 + j4];
  }
  // one gate element per thread
  const int er = tid >> 4, ec = tid & 15;
  float cst = carryC[(size_t)(mbase+er)*512 + ni*16 + ec];

  int baseA[2], sA[2], baseB[4], sB[4];
  #pragma unroll
  for (int q = 0; q < 2; q++){
    int ra = (q*8 + gID)*4 + tig;
    baseA[q] = ra*64; sA[q] = (ra & 7) << 2;
  }
  #pragma unroll
  for (int q = 0; q < 4; q++){
    int rb = (wN*32 + q*8 + gID)*4 + tig;
    baseB[q] = rb*64; sB[q] = (rb & 7) << 2;
  }

  for (int t = 0; t < TT; t++){
    const unsigned* hb = g_hbufU[t & 1];
    __half* hn = (__half*)g_hbufU[(t & 1) ^ 1];

    // As fill: 16 rows = 64 sub-rows x 16 uint4
    #pragma unroll
    for (int i = 0; i < 4; i++){
      int idx = tid + i*256;
      int r = idx >> 4, j4 = (idx & 15)*4;
      cpa16(&As2[r*64 + (j4 ^ ((r & 7) << 2))], &hb[(mbase*4 + r)*64 + j4]);
    }
    asm volatile("cp.async.commit_group;" ::: "memory");

    // prefetch Zx (fp16) + resets (overlaps cp.async)
    float pz[4]; int rc, rn;
    {
      const __half* zxr = (const __half*)g_zx +
                          ((size_t)t*128 + mbase + er)*NZ + ni*16 + ec;
      pz[0] = __half2float(__ldg(zxr));
      pz[1] = __half2float(__ldg(zxr + 512));
      pz[2] = __half2float(__ldg(zxr + 1024));
      pz[3] = __half2float(__ldg(zxr + 1536));
      rc = g_rst[t*128 + mbase + er];
      rn = (t == TT-1) ? 0 : g_rst[(t+1)*128 + mbase + er];
    }
    asm volatile("cp.async.wait_group 0;" ::: "memory");
    __syncthreads();

    {
      float acc[4][4];
      #pragma unroll
      for (int nb = 0; nb < 4; nb++)
        #pragma unroll
        for (int q = 0; q < 4; q++) acc[nb][q] = 0.f;

      #pragma unroll
      for (int jj = 0; jj < 16; jj += 4){
        int j = wK*16 + jj;
        uint4 av[2], bv[4];
        #pragma unroll
        for (int q = 0; q < 2; q++)
          av[q] = *(const uint4*)&As2[baseA[q] + (j ^ sA[q])];
        #pragma unroll
        for (int q = 0; q < 4; q++)
          bv[q] = *(const uint4*)&Bs2[baseB[q] + (j ^ sB[q])];
        unsigned Alo[4] = {av[0].x, av[1].x, av[0].y, av[1].y};
        unsigned Ahi[4] = {av[0].z, av[1].z, av[0].w, av[1].w};
        #pragma unroll
        for (int nb = 0; nb < 4; nb++){
          unsigned Blo[2] = {bv[nb].x, bv[nb].y};
          mma16(acc[nb], Alo, Blo);
          unsigned Bhi[2] = {bv[nb].z, bv[nb].w};
          mma16(acc[nb], Ahi, Bhi);
        }
      }
      float* z = Zs + wK*(16*64);
      int zr = gID;
      #pragma unroll
      for (int nb = 0; nb < 4; nb++){
        int zc = wN*32 + nb*8 + tig*2;
        z[zr*64 + zc]         = acc[nb][0];
        z[zr*64 + zc + 1]     = acc[nb][1];
        z[(zr+8)*64 + zc]     = acc[nb][2];
        z[(zr+8)*64 + zc + 1] = acc[nb][3];
      }
    }
    __syncthreads();

    {
      size_t rg = (size_t)t*128 + mbase + er;
      float zi = pz[0], zf = pz[1], zg = pz[2], zo = pz[3];
      #pragma unroll
      for (int k4 = 0; k4 < 4; k4++){
        const float* z = Zs + k4*(16*64) + er*64;
        zi += z[ec]; zf += z[16 + ec]; zg += z[32 + ec]; zo += z[48 + ec];
      }
      float cc = rc ? 0.f : cst;
      float ig = 1.f/(1.f + __expf(-zi));
      float fg = 1.f/(1.f + __expf(-zf));
      float og = 1.f/(1.f + __expf(-zo));
      cc = fg*cc + ig*tanhx(zg);
      float nh = og*tanhx(cc);
      cst = cc;
      int hcol = ni*16 + ec;

      unsigned yu = (unsigned)__half_as_ushort(__float2half(nh));
      unsigned yhi = __shfl_down_sync(0xffffffffu, yu, 1);
      unsigned hu = rn ? 0u : yu;
      unsigned hhi = __shfl_down_sync(0xffffffffu, hu, 1);
      if ((ec & 1) == 0){
        int pp = hcol >> 1;
        unsigned* hd = (unsigned*)hn + (((mbase+er)*4 + (pp & 3))*64 + (pp >> 2));
        asm volatile("st.global.cg.u32 [%0], %1;" :: "l"(hd), "r"(hu | (hhi << 16)) : "memory");
        unsigned* yd = (unsigned*)g_Ah + ((rg*512 + hcol) >> 1);
        asm volatile("st.global.cg.u32 [%0], %1;" :: "l"(yd), "r"(yu | (yhi << 16)) : "memory");
      }
      if (emb) emb[rg*512 + hcol] = nh;
      if (t == TT-1){
        coutP[(size_t)(mbase+er)*512 + hcol] = cc;
        houtP[(size_t)(mbase+er)*512 + hcol] = nh;
      }
    }
    if (t < TT-1) gbar_flag(mg, ni, (unsigned)(t + 1));
  }
}

// ---------------- logits ----------------
__global__ __launch_bounds__(256) void logits_k(
    const float* __restrict__ W, const float* __restrict__ b, float* __restrict__ C)
{
  __shared__ float Ws[512*20];
  int tid = threadIdx.x;
  for (int i = tid; i < 512*20; i += 256) Ws[i] = W[i];
  __syncthreads();
  int row = blockIdx.x*8 + (tid >> 5), lane = tid & 31;
  float acc[20];
  #pragma unroll
  for (int c = 0; c < 20; c++) acc[c] = 0.f;
  #pragma unroll 4
  for (int j = 0; j < 16; j++){
    float a = g_hpre[(size_t)row*512 + lane + j*32];
    const float* w = &Ws[(lane + j*32)*20];
    #pragma unroll
    for (int c = 0; c < 20; c++) acc[c] += a*w[c];
  }
  #pragma unroll
  for (int c = 0; c < 20; c++)
    #pragma unroll
    for (int o = 16; o; o >>= 1) acc[c] += __shfl_xor_sync(0xffffffffu, acc[c], o);
  if (lane < 20) C[(size_t)row*20 + lane] = acc[lane] + b[lane];
}

// ---------------- launcher ----------------
extern "C" void kernel_launch(void* const* d_in, const int*, int, void* d_out_, int){
  const float* x     = (const float*)d_in[0];
  const void*  rsts  = d_in[1];
  const float* cc    = (const float*)d_in[2];
  const float* ch    = (const float*)d_in[3];
  const float* preW  = (const float*)d_in[4];
  const float* preb  = (const float*)d_in[5];
  const float* lns   = (const float*)d_in[6];
  const float* lnb   = (const float*)d_in[7];
  const float* Wi0   = (const float*)d_in[8];
  const float* Wh0   = (const float*)d_in[9];
  const float* b0    = (const float*)d_in[10];
  const float* Wi1   = (const float*)d_in[11];
  const float* Wh1   = (const float*)d_in[12];
  const float* b1    = (const float*)d_in[13];
  const float* postW = (const float*)d_in[14];
  const float* postb = (const float*)d_in[15];
  const float* outW  = (const float*)d_in[16];
  const float* outb  = (const float*)d_in[17];
  float* out = (float*)d_out_;
  const size_t OC = 0, OH = 131072, OL = 262144, OE = 1572864;

  cudaFuncSetAttribute(gemm_h<false,false>, cudaFuncAttributeMaxDynamicSharedMemorySize, GEMM_SMEM);
  cudaFuncSetAttribute(gemm_h<false,true>,  cudaFuncAttributeMaxDynamicSharedMemorySize, GEMM_SMEM);
  cudaFuncSetAttribute(gemm_h<true,false>,  cudaFuncAttributeMaxDynamicSharedMemorySize, GEMM_SMEM);
  cudaFuncSetAttribute(rec_lstm, cudaFuncAttributeMaxDynamicSharedMemorySize, RECSMEM);

  detect_resets<<<1,256>>>((const unsigned char*)rsts);
  conv_resets<<<256,256>>>(rsts);
  dim3 g512(4,512), g2048(16,512);
  dim3 tp512(16,16), tp2048(64,16);

  conv_x<<<32768,256>>>(x, (size_t)TB*HH/4);
  pack_bh<<<tp512,256>>>(preW, 512);
  gemm_h<false,false><<<g512,256,GEMM_SMEM>>>(preb, 0, 512);
  ln_relu<<<8192,256>>>(lns, lnb);

  pack_bh<<<tp2048,256>>>(Wi0, 2048);
  gemm_h<false,true><<<g2048,256,GEMM_SMEM>>>(b0, 0, 2048);
  pack_wh<<<2048,512>>>(Wh0, 0);
  init_rec<<<256,256>>>(ch);
  rec_lstm<<<256,256,RECSMEM>>>(0, cc, nullptr, out + OC, out + OH);

  pack_bh<<<tp2048,256>>>(Wi1, 2048);
  gemm_h<false,true><<<g2048,256,GEMM_SMEM>>>(b1, 0, 2048);
  pack_wh<<<2048,512>>>(Wh1, 1);
  init_rec<<<256,256>>>(ch + 65536);
  rec_lstm<<<256,256,RECSMEM>>>(1, cc + 65536, out + OE,
                                out + OC + 65536, out + OH + 65536);

  pack_bh<<<tp512,256>>>(postW, 512);
  gemm_h<true,false><<<g512,256,GEMM_SMEM>>>(postb, 1, 512);
  logits_k<<<8192,256>>>(outW, outb, out + OL);
}